// round 14
// baseline (speedup 1.0000x reference)
#include <cuda_runtime.h>
#include <cuda_bf16.h>
#include <math.h>
#include <stdint.h>

#define DD   512
#define BB   512
#define TT   256
#define UDIM 32
#define NOBS 50
#define NTAYLOR 7
#define NSQUARE 2
#define NCTA 144
#define NSS  128   // supersteps

// ---------------- device scratch ----------------
__device__ float g_Y [DD*DD];
__device__ float g_E [DD*DD];
__device__ float g_P [DD*DD];
__device__ float g_T [DD*DD];
__device__ float g_T2[DD*DD];
__device__ float g_Bb[DD*UDIM];

__device__ __nv_bfloat16 g_Yht [DD*DD];
__device__ __nv_bfloat16 g_Ylt [DD*DD];
__device__ __nv_bfloat16 g_Eht [DD*DD];
__device__ __nv_bfloat16 g_Elt [DD*DD];
__device__ __nv_bfloat16 g_Pht [DD*DD];
__device__ __nv_bfloat16 g_Plt [DD*DD];
__device__ __nv_bfloat16 g_Pht2[DD*DD];
__device__ __nv_bfloat16 g_Plt2[DD*DD];

__device__ __nv_bfloat16 g_Ehi [DD*DD];
__device__ __nv_bfloat16 g_Elo [DD*DD];
__device__ __nv_bfloat16 g_E2hi[DD*DD];
__device__ __nv_bfloat16 g_E2lo[DD*DD];
__device__ __nv_bfloat16 g_Chi [64*DD];
__device__ __nv_bfloat16 g_Clo [64*DD];
__device__ __nv_bfloat16 g_Bbhi[DD*64];
__device__ __nv_bfloat16 g_Bblo[DD*64];
__device__ __nv_bfloat16 g_ABhi[DD*64];
__device__ __nv_bfloat16 g_ABlo[DD*64];
__device__ __nv_bfloat16 g_Dshi[64*64];
__device__ __nv_bfloat16 g_Dslo[64*64];

__device__ __nv_bfloat16 g_Zh [2*BB*DD];
__device__ __nv_bfloat16 g_Zl [2*BB*DD];
__device__ __nv_bfloat16 g_Zh2[2*BB*DD];
__device__ __nv_bfloat16 g_Zl2[2*BB*DD];
__device__ __nv_bfloat16 g_Uh[(size_t)TT*BB*64];
__device__ __nv_bfloat16 g_Ul[(size_t)TT*BB*64];

__device__ __align__(128) unsigned g_cnt[8*32];

// ---------------- helpers ----------------
__device__ __forceinline__ uint32_t smem_u32(const void* p) {
    uint32_t a;
    asm("{ .reg .u64 t; cvta.to.shared.u64 t, %1; cvt.u32.u64 %0, t; }" : "=r"(a) : "l"(p));
    return a;
}
#define SWZ(o) ((o) ^ (((o) >> 3) & 0x70))
#define BARH(id) asm volatile("bar.sync %0, 128;" :: "r"(id) : "memory")

__device__ __forceinline__ void ldmx4(uint32_t r[4], uint32_t addr) {
    asm volatile("ldmatrix.sync.aligned.m8n8.x4.shared.b16 {%0,%1,%2,%3}, [%4];"
        : "=r"(r[0]), "=r"(r[1]), "=r"(r[2]), "=r"(r[3]) : "r"(addr));
}
__device__ __forceinline__ void mma16816(float acc[4], const uint32_t a[4],
                                          uint32_t b0, uint32_t b1) {
    asm volatile("mma.sync.aligned.m16n8k16.row.col.f32.bf16.bf16.f32 "
        "{%0,%1,%2,%3},{%4,%5,%6,%7},{%8,%9},{%0,%1,%2,%3};"
        : "+f"(acc[0]), "+f"(acc[1]), "+f"(acc[2]), "+f"(acc[3])
        : "r"(a[0]), "r"(a[1]), "r"(a[2]), "r"(a[3]), "r"(b0), "r"(b1));
}
__device__ __forceinline__ void split4(float4 v, uint32_t hi_a, uint32_t lo_a) {
    __nv_bfloat162 h0 = __floats2bfloat162_rn(v.x, v.y);
    __nv_bfloat162 h1 = __floats2bfloat162_rn(v.z, v.w);
    __nv_bfloat162 l0 = __floats2bfloat162_rn(v.x - __bfloat162float(h0.x), v.y - __bfloat162float(h0.y));
    __nv_bfloat162 l1 = __floats2bfloat162_rn(v.z - __bfloat162float(h1.x), v.w - __bfloat162float(h1.y));
    uint32_t h0u = *(uint32_t*)&h0, h1u = *(uint32_t*)&h1;
    uint32_t l0u = *(uint32_t*)&l0, l1u = *(uint32_t*)&l1;
    asm volatile("st.shared.v2.b32 [%0], {%1,%2};" :: "r"(hi_a), "r"(h0u), "r"(h1u) : "memory");
    asm volatile("st.shared.v2.b32 [%0], {%1,%2};" :: "r"(lo_a), "r"(l0u), "r"(l1u) : "memory");
}
#define MMA_TRIPLE(accw, ahh, all, bhh, bll) \
    mma16816(accw[0][0], ahh##0, bhh[0], bhh[1]); \
    mma16816(accw[0][1], ahh##0, bhh[2], bhh[3]); \
    mma16816(accw[1][0], ahh##1, bhh[0], bhh[1]); \
    mma16816(accw[1][1], ahh##1, bhh[2], bhh[3]); \
    mma16816(accw[0][0], all##0, bhh[0], bhh[1]); \
    mma16816(accw[0][1], all##0, bhh[2], bhh[3]); \
    mma16816(accw[1][0], all##1, bhh[0], bhh[1]); \
    mma16816(accw[1][1], all##1, bhh[2], bhh[3]); \
    mma16816(accw[0][0], ahh##0, bll[0], bll[1]); \
    mma16816(accw[0][1], ahh##0, bll[2], bll[3]); \
    mma16816(accw[1][0], ahh##1, bll[0], bll[1]); \
    mma16816(accw[1][1], ahh##1, bll[2], bll[3]);

// ---------------- setup elementwise kernels ----------------
__global__ void build_Y_kernel(const float* __restrict__ skew, const float* __restrict__ gamma,
                               const float* __restrict__ dtp, float* __restrict__ Y)
{
    int idx = blockIdx.x*256 + threadIdx.x;
    if (idx >= DD*DD) return;
    int i = idx >> 9, j = idx & (DD-1);
    float v;
    if (i < j)      v =  skew[i*(DD-1) - (i*(i-1))/2 + (j-i-1)];
    else if (i > j) v = -skew[j*(DD-1) - (j*(j-1))/2 + (i-j-1)];
    else { float g = gamma[i]; v = -(fmaxf(g,0.f) + log1pf(expf(-fabsf(g)))); }
    Y[idx] = v * (dtp[0] * (1.0f/(float)(1<<NSQUARE)));
}
__global__ void init_EPT(float* E, float* P, float* Tm) {
    int idx = blockIdx.x*256 + threadIdx.x;
    if (idx >= DD*DD) return;
    float v = ((idx>>9) == (idx&(DD-1))) ? 1.f : 0.f;
    E[idx]=v; P[idx]=v; Tm[idx]=v;
}
__global__ void reset_barrier() { if (threadIdx.x < 8) g_cnt[threadIdx.x*32] = 0; }

__global__ void split_T(const float* __restrict__ src,
                        __nv_bfloat16* __restrict__ h, __nv_bfloat16* __restrict__ l)
{
    int idx = blockIdx.x*256 + threadIdx.x;
    if (idx >= DD*DD) return;
    int r = idx >> 9, c = idx & (DD-1);
    float v = src[idx];
    __nv_bfloat16 hh = __float2bfloat16(v);
    h[(size_t)c*DD + r] = hh;
    l[(size_t)c*DD + r] = __float2bfloat16(v - __bfloat162float(hh));
}
__global__ void split_mat(const float* __restrict__ src, __nv_bfloat16* hi, __nv_bfloat16* lo,
                          int rs, int cs, int rd, int cd, const float* dtp, int usedt)
{
    int idx = blockIdx.x*256 + threadIdx.x;
    if (idx >= rd*cd) return;
    int r = idx / cd, c = idx % cd;
    float v = (r < rs && c < cs) ? src[(size_t)r*cs + c] : 0.f;
    if (usedt) v *= dtp[0];
    __nv_bfloat16 h = __float2bfloat16(v);
    hi[idx] = h;
    lo[idx] = __float2bfloat16(v - __bfloat162float(h));
}

__global__ void gemm_small(float* __restrict__ C, const float* __restrict__ A,
                           const float* __restrict__ Bm)
{
    __shared__ float As[32][33];
    __shared__ float Bs[32][33];
    int tx = threadIdx.x & 15, ty = threadIdx.x >> 4;
    int i0 = blockIdx.x*32;
    float a00=0,a01=0,a10=0,a11=0;
    for (int k0 = 0; k0 < DD; k0 += 32) {
        for (int u = threadIdx.x; u < 32*32; u += 256) {
            int r = u>>5, c = u&31;
            As[r][c] = A[(size_t)(i0+r)*DD + k0+c];
            Bs[r][c] = Bm[(size_t)(k0+r)*UDIM + c];
        }
        __syncthreads();
        #pragma unroll
        for (int k = 0; k < 32; k++) {
            float x0=As[ty*2][k], x1=As[ty*2+1][k];
            float y0=Bs[k][tx*2], y1=Bs[k][tx*2+1];
            a00+=x0*y0; a01+=x0*y1; a10+=x1*y0; a11+=x1*y1;
        }
        __syncthreads();
    }
    C[(size_t)(i0+ty*2+0)*UDIM + tx*2+0]=a00;
    C[(size_t)(i0+ty*2+0)*UDIM + tx*2+1]=a01;
    C[(size_t)(i0+ty*2+1)*UDIM + tx*2+0]=a10;
    C[(size_t)(i0+ty*2+1)*UDIM + tx*2+1]=a11;
}

// ---------------- tensor-core setup GEMM (R13 + mode 0 plain) ----------------
#define TC_BH  0u
#define TC_BL  32768u
#define TC_ZR  65536u
#define TC_TOT 131072u

__global__ void __launch_bounds__(256) gemm_tc(
    const float* __restrict__ A,
    const __nv_bfloat16* __restrict__ Bh0, const __nv_bfloat16* __restrict__ Bl0,
    const __nv_bfloat16* __restrict__ Bh1, const __nv_bfloat16* __restrict__ Bl1,
    float* __restrict__ C0, float* __restrict__ C1,
    float* __restrict__ Eacc, float* __restrict__ Pacc, const float* __restrict__ Pin,
    __nv_bfloat16* __restrict__ Th0, __nv_bfloat16* __restrict__ Tl0,
    __nv_bfloat16* __restrict__ Th1, __nv_bfloat16* __restrict__ Tl1,
    float invk, float invk1, int mode)
{
    extern __shared__ __align__(1024) char smem[];
    const int tid = threadIdx.x, lane = tid & 31, w = tid >> 5;
    const int half = w >> 2, wsub = w & 3;
    const int wm = (wsub & 1)*32, wn = (wsub >> 1)*16;
    const int htid = tid & 127;
    const int barid = 1 + half;
    const int n0 = blockIdx.x*32, m0 = blockIdx.y*64;
    const int z = blockIdx.z;
    const __nv_bfloat16* Bh = z ? Bh1 : Bh0;
    const __nv_bfloat16* Bl = z ? Bl1 : Bl0;
    const uint32_t sb = smem_u32(smem);

    #pragma unroll
    for (int i = 0; i < 8; i++) {
        int idx = i*256 + tid;
        int r = idx >> 6, g = idx & 63;
        uint32_t soff = (uint32_t)((g>>3)*4096) + SWZ((uint32_t)(r*128 + (g&7)*16));
        *(uint4*)(smem + TC_BH + soff) = *(const uint4*)(Bh + (size_t)(n0+r)*DD + g*8);
        *(uint4*)(smem + TC_BL + soff) = *(const uint4*)(Bl + (size_t)(n0+r)*DD + g*8);
    }
    __syncthreads();

    const uint32_t aoff0 = (uint32_t)((wm + 0  + (lane & 15))*128 + ((lane >> 4) << 4));
    const uint32_t aoff1 = (uint32_t)((wm + 16 + (lane & 15))*128 + ((lane >> 4) << 4));
    const uint32_t boff  = (uint32_t)((wn + (lane & 7) + ((lane >> 4) & 1)*8)*128 + ((lane >> 3) & 1)*16);
    const int ldr = htid >> 4, lfq = htid & 15;
    const uint32_t ringb = TC_ZR + (uint32_t)half*32768u;
    const int gs0 = half*4;

    float acc[2][2][4];
    #pragma unroll
    for (int a = 0; a < 2; a++)
        #pragma unroll
        for (int b = 0; b < 2; b++)
            #pragma unroll
            for (int c = 0; c < 4; c++) acc[a][b][c] = 0.f;

    float4 pf[8];
    #pragma unroll
    for (int i = 0; i < 8; i++)
        pf[i] = *(const float4*)(A + (size_t)(m0 + i*8 + ldr)*DD + gs0*64 + lfq*4);
    {
        uint32_t zb = sb + ringb + 16384u;
        #pragma unroll
        for (int i = 0; i < 8; i++) {
            uint32_t off = SWZ((uint32_t)((i*8+ldr)*128 + lfq*8));
            split4(pf[i], zb + off, zb + 8192u + off);
        }
    }
    BARH(barid);

    for (int s = 0; s < 4; s++) {
        int gs = gs0 + s;
        if (s + 1 < 4) {
            #pragma unroll
            for (int i = 0; i < 8; i++)
                pf[i] = *(const float4*)(A + (size_t)(m0 + i*8 + ldr)*DD + (gs+1)*64 + lfq*4);
        }
        {
            uint32_t zb = sb + ringb + (uint32_t)((s+1) & 1)*16384u;
            uint32_t bb = sb + TC_BH + (uint32_t)gs*4096u;
            #pragma unroll
            for (int k16 = 0; k16 < 4; k16++) {
                uint32_t ah0[4], al0[4], ah1[4], al1[4], bh[4], bl[4];
                uint32_t ad0 = zb + SWZ(aoff0 + (uint32_t)k16*32);
                ldmx4(ah0, ad0); ldmx4(al0, ad0 + 8192u);
                uint32_t ad1 = zb + SWZ(aoff1 + (uint32_t)k16*32);
                ldmx4(ah1, ad1); ldmx4(al1, ad1 + 8192u);
                uint32_t bd = bb + SWZ(boff + (uint32_t)k16*32);
                ldmx4(bh, bd); ldmx4(bl, bd + 32768u);
                MMA_TRIPLE(acc, ah, al, bh, bl)
            }
        }
        BARH(barid);
        if (s + 1 < 4) {
            uint32_t zb = sb + ringb + (uint32_t)(s & 1)*16384u;
            #pragma unroll
            for (int i = 0; i < 8; i++) {
                uint32_t off = SWZ((uint32_t)((i*8+ldr)*128 + lfq*8));
                split4(pf[i], zb + off, zb + 8192u + off);
            }
            BARH(barid);
        }
    }

    __syncthreads();
    if (half == 1) {
        uint32_t ra = sb + TC_ZR + 32768u + (uint32_t)htid*64u;
        #pragma unroll
        for (int mi = 0; mi < 2; mi++)
            #pragma unroll
            for (int ni = 0; ni < 2; ni++)
                asm volatile("st.shared.v4.b32 [%0], {%1,%2,%3,%4};"
                    :: "r"(ra + (uint32_t)(mi*2+ni)*16u),
                       "r"(__float_as_uint(acc[mi][ni][0])), "r"(__float_as_uint(acc[mi][ni][1])),
                       "r"(__float_as_uint(acc[mi][ni][2])), "r"(__float_as_uint(acc[mi][ni][3])) : "memory");
    }
    __syncthreads();
    if (half != 0) return;
    {
        const float* red = (const float*)(smem + TC_ZR + 32768u) + htid*16;
        #pragma unroll
        for (int mi = 0; mi < 2; mi++)
            #pragma unroll
            for (int ni = 0; ni < 2; ni++)
                #pragma unroll
                for (int c = 0; c < 4; c++)
                    acc[mi][ni][c] += red[(mi*2+ni)*4 + c];
    }

    int r0 = m0 + wm + (lane >> 2);
    int c0 = n0 + wn + (lane & 3)*2;
    float* Cw = z ? C1 : C0;
    __nv_bfloat16* Th = z ? Th1 : Th0;
    __nv_bfloat16* Tl = z ? Tl1 : Tl0;

    #pragma unroll
    for (int mi = 0; mi < 2; mi++)
        #pragma unroll
        for (int ni = 0; ni < 2; ni++)
            #pragma unroll
            for (int h = 0; h < 2; h++) {
                int rr = r0 + mi*16 + h*8, cc = c0 + ni*8;
                size_t idx = (size_t)rr*DD + cc;
                float v0 = acc[mi][ni][h*2+0];
                float v1 = acc[mi][ni][h*2+1];
                if (mode == 1) {
                    v0 *= invk; v1 *= invk;
                    *(float2*)(Cw + idx) = make_float2(v0, v1);
                    float2 e = *(float2*)(Eacc + idx);
                    e.x += v0; e.y += v1;
                    *(float2*)(Eacc + idx) = e;
                    float2 p = *(float2*)(Pacc + idx);
                    p.x += v0*invk1; p.y += v1*invk1;
                    *(float2*)(Pacc + idx) = p;
                } else {
                    if (mode != 0 && z == 0) {
                        float2 pin = *(const float2*)(Pin + idx);
                        v0 = 0.5f*v0 + 0.5f*pin.x;
                        v1 = 0.5f*v1 + 0.5f*pin.y;
                    }
                    *(float2*)(Cw + idx) = make_float2(v0, v1);
                    if (mode == 2) {
                        __nv_bfloat16 h0 = __float2bfloat16(v0);
                        __nv_bfloat16 h1 = __float2bfloat16(v1);
                        Th[(size_t)cc*DD + rr]     = h0;
                        Tl[(size_t)cc*DD + rr]     = __float2bfloat16(v0 - __bfloat162float(h0));
                        Th[(size_t)(cc+1)*DD + rr] = h1;
                        Tl[(size_t)(cc+1)*DD + rr] = __float2bfloat16(v1 - __bfloat162float(h1));
                    }
                }
            }
}

// ---------------- persistent scan: 2-step supersteps ----------------
// Z layout: E hi/lo 64K | E2 hi/lo 64K | Bb 8K | ABb 8K | ustage 16K | ring 2x16K
#define ZBEH  0u
#define ZBEL  32768u
#define ZE2H  65536u
#define ZE2L  98304u
#define ZBBH  131072u
#define ZBBL  135168u
#define ZABH  139264u
#define ZABL  143360u
#define ZUST  147456u
#define ZRING 163840u
// Y layout: C hi/lo 64K | Ds 8K | red 8K | rings at 147456 + half*32768
#define YBH   0u
#define YBL   32768u
#define YDH   131072u
#define YDL   135168u
#define YRED  139264u
#define YRING 147456u
#define SM_TOT 212992u

__device__ __forceinline__ void gb_arrive(int blk) {
    __syncthreads();
    if (threadIdx.x == 0) {
        __threadfence();
        atomicAdd(&g_cnt[(blk & 7)*32], 1u);
    }
}
__device__ __forceinline__ void gb_wait(unsigned want) {
    if (threadIdx.x == 0) {
        unsigned s;
        do {
            s = 0;
            #pragma unroll
            for (int i = 0; i < 8; i++) s += *(volatile unsigned*)&g_cnt[i*32];
        } while (s < want);
        __threadfence();
    }
    __syncthreads();
}

__global__ void __launch_bounds__(256) scan_persist(
    float* __restrict__ Zo, float* __restrict__ Yo,
    const __nv_bfloat16* __restrict__ Ehi,  const __nv_bfloat16* __restrict__ Elo,
    const __nv_bfloat16* __restrict__ E2hi, const __nv_bfloat16* __restrict__ E2lo,
    const __nv_bfloat16* __restrict__ Bbhi, const __nv_bfloat16* __restrict__ Bblo,
    const __nv_bfloat16* __restrict__ ABhi, const __nv_bfloat16* __restrict__ ABlo,
    const __nv_bfloat16* __restrict__ Chi,  const __nv_bfloat16* __restrict__ Clo,
    const __nv_bfloat16* __restrict__ Dshi, const __nv_bfloat16* __restrict__ Dslo,
    __nv_bfloat16* __restrict__ Zh,  __nv_bfloat16* __restrict__ Zl,
    __nv_bfloat16* __restrict__ Zh2, __nv_bfloat16* __restrict__ Zl2,
    const __nv_bfloat16* __restrict__ Uh, const __nv_bfloat16* __restrict__ Ul)
{
    extern __shared__ __align__(1024) char smem[];
    const int tid  = threadIdx.x;
    const int lane = tid & 31;
    const int w    = tid >> 5;
    const int half = w >> 2;
    const int wsub = w & 3;
    const int wm = (wsub & 1) * 32;
    const int wn = (wsub >> 1) * 16;
    const int htid = tid & 127;
    const int barid = 1 + half;
    const int blk = blockIdx.x;
    const bool isZ = blk < 128;
    const uint32_t sb = smem_u32(smem);

    const uint32_t aoff0 = (uint32_t)((wm + 0  + (lane & 15))*128 + ((lane >> 4) << 4));
    const uint32_t aoff1 = (uint32_t)((wm + 16 + (lane & 15))*128 + ((lane >> 4) << 4));
    const uint32_t boff  = (uint32_t)((wn + (lane & 7) + ((lane >> 4) & 1)*8)*128 + ((lane >> 3) & 1)*16);

    int m0, n0;
    if (isZ) { m0 = (blk >> 4) * 64; n0 = (blk & 15) * 32; }
    else     { int local = blk - 128; m0 = (local >> 1) * 64; n0 = (local & 1) * 32; }

    // ---- resident B operands ----
    if (isZ) {
        #pragma unroll
        for (int i = 0; i < 8; i++) {
            int idx = i*256 + tid;
            int r = idx >> 6, g = idx & 63;
            uint32_t soff = (uint32_t)((g >> 3)*4096) + SWZ((uint32_t)(r*128 + (g & 7)*16));
            *(uint4*)(smem + ZBEH + soff) = *(const uint4*)(Ehi  + (size_t)(n0 + r)*DD + g*8);
            *(uint4*)(smem + ZBEL + soff) = *(const uint4*)(Elo  + (size_t)(n0 + r)*DD + g*8);
            *(uint4*)(smem + ZE2H + soff) = *(const uint4*)(E2hi + (size_t)(n0 + r)*DD + g*8);
            *(uint4*)(smem + ZE2L + soff) = *(const uint4*)(E2lo + (size_t)(n0 + r)*DD + g*8);
        }
        {
            int r = tid >> 3, g = tid & 7;
            uint32_t soff = SWZ((uint32_t)(r*128 + g*16));
            *(uint4*)(smem + ZBBH + soff) = *(const uint4*)(Bbhi + (size_t)(n0 + r)*64 + g*8);
            *(uint4*)(smem + ZBBL + soff) = *(const uint4*)(Bblo + (size_t)(n0 + r)*64 + g*8);
            *(uint4*)(smem + ZABH + soff) = *(const uint4*)(ABhi + (size_t)(n0 + r)*64 + g*8);
            *(uint4*)(smem + ZABL + soff) = *(const uint4*)(ABlo + (size_t)(n0 + r)*64 + g*8);
        }
    } else {
        #pragma unroll
        for (int i = 0; i < 8; i++) {
            int idx = i*256 + tid;
            int r = idx >> 6, g = idx & 63;
            uint32_t soff = (uint32_t)((g >> 3)*4096) + SWZ((uint32_t)(r*128 + (g & 7)*16));
            *(uint4*)(smem + YBH + soff) = *(const uint4*)(Chi + (size_t)(n0 + r)*DD + g*8);
            *(uint4*)(smem + YBL + soff) = *(const uint4*)(Clo + (size_t)(n0 + r)*DD + g*8);
        }
        {
            int r = tid >> 3, g = tid & 7;
            uint32_t soff = SWZ((uint32_t)(r*128 + g*16));
            *(uint4*)(smem + YDH + soff) = *(const uint4*)(Dshi + (size_t)(n0 + r)*64 + g*8);
            *(uint4*)(smem + YDL + soff) = *(const uint4*)(Dslo + (size_t)(n0 + r)*64 + g*8);
        }
    }
    __syncthreads();

    for (int ss = 0; ss <= NSS; ss++) {
        const bool activeZ = isZ && (ss < NSS);
        const bool activeY = (!isZ) && (ss >= 1);
        float acc[2][2][4];

        if (activeZ) {
            #pragma unroll
            for (int a = 0; a < 2; a++)
                #pragma unroll
                for (int b = 0; b < 2; b++)
                    #pragma unroll
                    for (int c = 0; c < 4; c++) acc[a][b][c] = 0.f;

            // ---- u phase (pre-barrier) ----
            const __nv_bfloat16* uh0 = Uh + (size_t)(2*ss)*BB*64;
            const __nv_bfloat16* ul0 = Ul + (size_t)(2*ss)*BB*64;
            #pragma unroll
            for (int i = 0; i < 2; i++) {
                int idx = i*256 + tid;
                int r = idx >> 3, g = idx & 7;
                uint32_t off = SWZ((uint32_t)(r*128 + g*16));
                *(uint4*)(smem + ZUST + off)         = *(const uint4*)(uh0 + (size_t)(m0 + r)*64 + g*8);
                *(uint4*)(smem + ZUST + 8192u + off) = *(const uint4*)(ul0 + (size_t)(m0 + r)*64 + g*8);
            }
            __syncthreads();
            {
                uint32_t bb = sb + (half ? ZABH : ZBBH);
                #pragma unroll
                for (int k16 = 0; k16 < 4; k16++) {
                    uint32_t ah0[4], al0[4], ah1[4], al1[4], bh[4], bl[4];
                    uint32_t ad0 = sb + ZUST + SWZ(aoff0 + (uint32_t)k16*32);
                    ldmx4(ah0, ad0); ldmx4(al0, ad0 + 8192u);
                    uint32_t ad1 = sb + ZUST + SWZ(aoff1 + (uint32_t)k16*32);
                    ldmx4(ah1, ad1); ldmx4(al1, ad1 + 8192u);
                    uint32_t bd = bb + SWZ(boff + (uint32_t)k16*32);
                    ldmx4(bh, bd); ldmx4(bl, bd + 4096u);
                    MMA_TRIPLE(acc, ah, al, bh, bl)
                }
            }
            __syncthreads();
            const __nv_bfloat16* uh1 = Uh + (size_t)(2*ss+1)*BB*64;
            const __nv_bfloat16* ul1 = Ul + (size_t)(2*ss+1)*BB*64;
            #pragma unroll
            for (int i = 0; i < 2; i++) {
                int idx = i*256 + tid;
                int r = idx >> 3, g = idx & 7;
                uint32_t off = SWZ((uint32_t)(r*128 + g*16));
                *(uint4*)(smem + ZUST + off)         = *(const uint4*)(uh1 + (size_t)(m0 + r)*64 + g*8);
                *(uint4*)(smem + ZUST + 8192u + off) = *(const uint4*)(ul1 + (size_t)(m0 + r)*64 + g*8);
            }
            __syncthreads();
            if (half == 1) {
                uint32_t bb = sb + ZBBH;
                #pragma unroll
                for (int k16 = 0; k16 < 4; k16++) {
                    uint32_t ah0[4], al0[4], ah1[4], al1[4], bh[4], bl[4];
                    uint32_t ad0 = sb + ZUST + SWZ(aoff0 + (uint32_t)k16*32);
                    ldmx4(ah0, ad0); ldmx4(al0, ad0 + 8192u);
                    uint32_t ad1 = sb + ZUST + SWZ(aoff1 + (uint32_t)k16*32);
                    ldmx4(ah1, ad1); ldmx4(al1, ad1 + 8192u);
                    uint32_t bd = bb + SWZ(boff + (uint32_t)k16*32);
                    ldmx4(bh, bd); ldmx4(bl, bd + 4096u);
                    MMA_TRIPLE(acc, ah, al, bh, bl)
                }
            }
        }
        if (ss > 0) gb_wait((unsigned)NCTA * (unsigned)ss);

        if (activeZ) {
            const __nv_bfloat16* zh = Zh + (size_t)(ss & 1)*BB*DD;
            const __nv_bfloat16* zl = Zl + (size_t)(ss & 1)*BB*DD;
            uint4 ph[2], pl[2];
            #pragma unroll
            for (int i = 0; i < 2; i++) {
                int idx = i*256 + tid;
                int r = idx >> 3, g = idx & 7;
                ph[i] = *(const uint4*)(zh + (size_t)(m0 + r)*DD + g*8);
                pl[i] = *(const uint4*)(zl + (size_t)(m0 + r)*DD + g*8);
            }
            #pragma unroll
            for (int i = 0; i < 2; i++) {
                int idx = i*256 + tid;
                int r = idx >> 3, g = idx & 7;
                uint32_t off = SWZ((uint32_t)(r*128 + g*16));
                *(uint4*)(smem + ZRING + 16384u + off)         = ph[i];
                *(uint4*)(smem + ZRING + 16384u + 8192u + off) = pl[i];
            }
            #pragma unroll
            for (int i = 0; i < 2; i++) {
                int idx = i*256 + tid;
                int r = idx >> 3, g = idx & 7;
                ph[i] = *(const uint4*)(zh + (size_t)(m0 + r)*DD + 64 + g*8);
                pl[i] = *(const uint4*)(zl + (size_t)(m0 + r)*DD + 64 + g*8);
            }
            __syncthreads();

            const uint32_t bhalf = half ? ZE2H : ZBEH;
            for (int s = 0; s < 8; s++) {
                {
                    uint32_t zb = sb + ZRING + (uint32_t)((s+1) & 1)*16384u;
                    uint32_t bb = sb + bhalf + (uint32_t)s*4096u;
                    #pragma unroll
                    for (int k16 = 0; k16 < 4; k16++) {
                        uint32_t ah0[4], al0[4], ah1[4], al1[4], bh[4], bl[4];
                        uint32_t ad0 = zb + SWZ(aoff0 + (uint32_t)k16*32);
                        ldmx4(ah0, ad0); ldmx4(al0, ad0 + 8192u);
                        uint32_t ad1 = zb + SWZ(aoff1 + (uint32_t)k16*32);
                        ldmx4(ah1, ad1); ldmx4(al1, ad1 + 8192u);
                        uint32_t bd = bb + SWZ(boff + (uint32_t)k16*32);
                        ldmx4(bh, bd); ldmx4(bl, bd + 32768u);
                        MMA_TRIPLE(acc, ah, al, bh, bl)
                    }
                }
                __syncthreads();
                if (s + 1 < 8) {
                    #pragma unroll
                    for (int i = 0; i < 2; i++) {
                        int idx = i*256 + tid;
                        int r = idx >> 3, g = idx & 7;
                        uint32_t off = SWZ((uint32_t)(r*128 + g*16));
                        *(uint4*)(smem + ZRING + (uint32_t)(s & 1)*16384u + off)         = ph[i];
                        *(uint4*)(smem + ZRING + (uint32_t)(s & 1)*16384u + 8192u + off) = pl[i];
                    }
                    if (s + 2 < 8) {
                        #pragma unroll
                        for (int i = 0; i < 2; i++) {
                            int idx = i*256 + tid;
                            int r = idx >> 3, g = idx & 7;
                            ph[i] = *(const uint4*)(zh + (size_t)(m0 + r)*DD + (s+2)*64 + g*8);
                            pl[i] = *(const uint4*)(zl + (size_t)(m0 + r)*DD + (s+2)*64 + g*8);
                        }
                    }
                    __syncthreads();
                }
            }

            // ---- epilogue: each half owns one timestep ----
            int r0 = m0 + wm + (lane >> 2);
            int c0 = n0 + wn + (lane & 3)*2;
            float* Zout = Zo + (size_t)(2*ss + half)*BB*DD;
            __nv_bfloat16* zhn = half ? (Zh  + (size_t)((ss+1) & 1)*BB*DD)
                                      : (Zh2 + (size_t)(ss & 1)*BB*DD);
            __nv_bfloat16* zln = half ? (Zl  + (size_t)((ss+1) & 1)*BB*DD)
                                      : (Zl2 + (size_t)(ss & 1)*BB*DD);
            #pragma unroll
            for (int mi = 0; mi < 2; mi++)
                #pragma unroll
                for (int ni = 0; ni < 2; ni++) {
                    int row = r0 + mi*16, col = c0 + ni*8;
                    float a0 = acc[mi][ni][0], a1 = acc[mi][ni][1];
                    float a2 = acc[mi][ni][2], a3 = acc[mi][ni][3];
                    *(float2*)(Zout + (size_t)row*DD + col)     = make_float2(a0, a1);
                    *(float2*)(Zout + (size_t)(row+8)*DD + col) = make_float2(a2, a3);
                    __nv_bfloat162 h0 = __floats2bfloat162_rn(a0, a1);
                    __nv_bfloat162 l0 = __floats2bfloat162_rn(a0 - __bfloat162float(h0.x),
                                                              a1 - __bfloat162float(h0.y));
                    __nv_bfloat162 h1 = __floats2bfloat162_rn(a2, a3);
                    __nv_bfloat162 l1 = __floats2bfloat162_rn(a2 - __bfloat162float(h1.x),
                                                              a3 - __bfloat162float(h1.y));
                    *(__nv_bfloat162*)(zhn + (size_t)row*DD + col)     = h0;
                    *(__nv_bfloat162*)(zln + (size_t)row*DD + col)     = l0;
                    *(__nv_bfloat162*)(zhn + (size_t)(row+8)*DD + col) = h1;
                    *(__nv_bfloat162*)(zln + (size_t)(row+8)*DD + col) = l1;
                }
        }

        if (activeY) {
            const int ldr = htid >> 3, ldg = htid & 7;
            const int gs0 = half*4;
            const uint32_t ringb = YRING + (uint32_t)half*32768u;
            for (int p = 0; p < 2; p++) {
                int tau = 2*ss - 2 + p;
                const __nv_bfloat16* zh = p ? (Zh  + (size_t)(ss & 1)*BB*DD)
                                            : (Zh2 + (size_t)((ss-1) & 1)*BB*DD);
                const __nv_bfloat16* zl = p ? (Zl  + (size_t)(ss & 1)*BB*DD)
                                            : (Zl2 + (size_t)((ss-1) & 1)*BB*DD);
                #pragma unroll
                for (int a = 0; a < 2; a++)
                    #pragma unroll
                    for (int b = 0; b < 2; b++)
                        #pragma unroll
                        for (int c = 0; c < 4; c++) acc[a][b][c] = 0.f;

                if (half == 0) {
                    const __nv_bfloat16* uh = Uh + (size_t)tau*BB*64;
                    const __nv_bfloat16* ul = Ul + (size_t)tau*BB*64;
                    #pragma unroll
                    for (int i = 0; i < 4; i++) {
                        int r = i*16 + ldr;
                        uint32_t off = SWZ((uint32_t)(r*128 + ldg*16));
                        *(uint4*)(smem + ringb + off)         = *(const uint4*)(uh + (size_t)(m0 + r)*64 + ldg*8);
                        *(uint4*)(smem + ringb + 8192u + off) = *(const uint4*)(ul + (size_t)(m0 + r)*64 + ldg*8);
                    }
                    BARH(barid);
                    #pragma unroll
                    for (int k16 = 0; k16 < 4; k16++) {
                        uint32_t ah0[4], al0[4], ah1[4], al1[4], bh[4], bl[4];
                        uint32_t ad0 = sb + ringb + SWZ(aoff0 + (uint32_t)k16*32);
                        ldmx4(ah0, ad0); ldmx4(al0, ad0 + 8192u);
                        uint32_t ad1 = sb + ringb + SWZ(aoff1 + (uint32_t)k16*32);
                        ldmx4(ah1, ad1); ldmx4(al1, ad1 + 8192u);
                        uint32_t bd = sb + YDH + SWZ(boff + (uint32_t)k16*32);
                        ldmx4(bh, bd); ldmx4(bl, bd + 4096u);
                        MMA_TRIPLE(acc, ah, al, bh, bl)
                    }
                }
                uint4 ph[4], pl[4];
                #pragma unroll
                for (int i = 0; i < 4; i++) {
                    int r = i*16 + ldr;
                    ph[i] = *(const uint4*)(zh + (size_t)(m0 + r)*DD + gs0*64 + ldg*8);
                    pl[i] = *(const uint4*)(zl + (size_t)(m0 + r)*DD + gs0*64 + ldg*8);
                }
                if (half == 0) BARH(barid);   // ensure u-phase ldmatrix done before slot reuse
                #pragma unroll
                for (int i = 0; i < 4; i++) {
                    int r = i*16 + ldr;
                    uint32_t off = SWZ((uint32_t)(r*128 + ldg*16));
                    *(uint4*)(smem + ringb + 16384u + off)         = ph[i];
                    *(uint4*)(smem + ringb + 16384u + 8192u + off) = pl[i];
                }
                #pragma unroll
                for (int i = 0; i < 4; i++) {
                    int r = i*16 + ldr;
                    ph[i] = *(const uint4*)(zh + (size_t)(m0 + r)*DD + (gs0+1)*64 + ldg*8);
                    pl[i] = *(const uint4*)(zl + (size_t)(m0 + r)*DD + (gs0+1)*64 + ldg*8);
                }
                BARH(barid);

                for (int s = 0; s < 4; s++) {
                    int gs = gs0 + s;
                    {
                        uint32_t zb = sb + ringb + (uint32_t)((s+1) & 1)*16384u;
                        uint32_t bb = sb + YBH + (uint32_t)gs*4096u;
                        #pragma unroll
                        for (int k16 = 0; k16 < 4; k16++) {
                            uint32_t ah0[4], al0[4], ah1[4], al1[4], bh[4], bl[4];
                            uint32_t ad0 = zb + SWZ(aoff0 + (uint32_t)k16*32);
                            ldmx4(ah0, ad0); ldmx4(al0, ad0 + 8192u);
                            uint32_t ad1 = zb + SWZ(aoff1 + (uint32_t)k16*32);
                            ldmx4(ah1, ad1); ldmx4(al1, ad1 + 8192u);
                            uint32_t bd = bb + SWZ(boff + (uint32_t)k16*32);
                            ldmx4(bh, bd); ldmx4(bl, bd + 32768u);
                            MMA_TRIPLE(acc, ah, al, bh, bl)
                        }
                    }
                    BARH(barid);
                    if (s + 1 < 4) {
                        #pragma unroll
                        for (int i = 0; i < 4; i++) {
                            int r = i*16 + ldr;
                            uint32_t off = SWZ((uint32_t)(r*128 + ldg*16));
                            *(uint4*)(smem + ringb + (uint32_t)(s & 1)*16384u + off)         = ph[i];
                            *(uint4*)(smem + ringb + (uint32_t)(s & 1)*16384u + 8192u + off) = pl[i];
                        }
                        if (s + 2 < 4) {
                            #pragma unroll
                            for (int i = 0; i < 4; i++) {
                                int r = i*16 + ldr;
                                ph[i] = *(const uint4*)(zh + (size_t)(m0 + r)*DD + (gs+2)*64 + ldg*8);
                                pl[i] = *(const uint4*)(zl + (size_t)(m0 + r)*DD + (gs+2)*64 + ldg*8);
                            }
                        }
                        BARH(barid);
                    }
                }

                __syncthreads();
                if (half == 1) {
                    uint32_t ra = sb + YRED + (uint32_t)htid*64u;
                    #pragma unroll
                    for (int mi = 0; mi < 2; mi++)
                        #pragma unroll
                        for (int ni = 0; ni < 2; ni++)
                            asm volatile("st.shared.v4.b32 [%0], {%1,%2,%3,%4};"
                                :: "r"(ra + (uint32_t)(mi*2+ni)*16u),
                                   "r"(__float_as_uint(acc[mi][ni][0])), "r"(__float_as_uint(acc[mi][ni][1])),
                                   "r"(__float_as_uint(acc[mi][ni][2])), "r"(__float_as_uint(acc[mi][ni][3])) : "memory");
                }
                __syncthreads();
                if (half == 0) {
                    const float* red = (const float*)(smem + YRED) + htid*16;
                    #pragma unroll
                    for (int mi = 0; mi < 2; mi++)
                        #pragma unroll
                        for (int ni = 0; ni < 2; ni++)
                            #pragma unroll
                            for (int c = 0; c < 4; c++)
                                acc[mi][ni][c] += red[(mi*2+ni)*4 + c];
                    int r0 = m0 + wm + (lane >> 2);
                    int c0 = n0 + wn + (lane & 3)*2;
                    float* Yout = Yo + (size_t)tau*BB*NOBS;
                    #pragma unroll
                    for (int mi = 0; mi < 2; mi++)
                        #pragma unroll
                        for (int ni = 0; ni < 2; ni++) {
                            int row = r0 + mi*16, col = c0 + ni*8;
                            if (col < NOBS)     Yout[(size_t)row*NOBS + col]       = acc[mi][ni][0];
                            if (col + 1 < NOBS) Yout[(size_t)row*NOBS + col + 1]   = acc[mi][ni][1];
                            if (col < NOBS)     Yout[(size_t)(row+8)*NOBS + col]   = acc[mi][ni][2];
                            if (col + 1 < NOBS) Yout[(size_t)(row+8)*NOBS + col+1] = acc[mi][ni][3];
                        }
                }
                __syncthreads();
            }
        }
        if (ss < NSS) gb_arrive(blk);
    }
}

// ---------------- host orchestration ----------------
extern "C" void kernel_launch(void* const* d_in, const int* in_sizes, int n_in,
                              void* d_out, int out_size)
{
    const float* z_dyn = (const float*)d_in[0];
    const float* dtp   = (const float*)d_in[2];
    const float* U     = (const float*)d_in[3];
    const float* skew  = (const float*)d_in[4];
    const float* gamma = (const float*)d_in[5];
    const float* B_ct  = (const float*)d_in[6];
    const float* Cm    = (const float*)d_in[7];
    const float* Dm    = (const float*)d_in[8];

    float *Y_, *E_, *P_, *T_, *T2_, *Bb_;
    cudaGetSymbolAddress((void**)&Y_,  g_Y);
    cudaGetSymbolAddress((void**)&E_,  g_E);
    cudaGetSymbolAddress((void**)&P_,  g_P);
    cudaGetSymbolAddress((void**)&T_,  g_T);
    cudaGetSymbolAddress((void**)&T2_, g_T2);
    cudaGetSymbolAddress((void**)&Bb_, g_Bb);

    __nv_bfloat16 *Yht, *Ylt, *Eht, *Elt, *Pht, *Plt, *Pht2, *Plt2;
    __nv_bfloat16 *Ehi, *Elo, *E2hi, *E2lo, *Chi, *Clo, *Bbhi, *Bblo, *ABhi, *ABlo, *Dshi, *Dslo;
    __nv_bfloat16 *Zh, *Zl, *Zh2, *Zl2, *Uh, *Ul;
    cudaGetSymbolAddress((void**)&Yht,  g_Yht);
    cudaGetSymbolAddress((void**)&Ylt,  g_Ylt);
    cudaGetSymbolAddress((void**)&Eht,  g_Eht);
    cudaGetSymbolAddress((void**)&Elt,  g_Elt);
    cudaGetSymbolAddress((void**)&Pht,  g_Pht);
    cudaGetSymbolAddress((void**)&Plt,  g_Plt);
    cudaGetSymbolAddress((void**)&Pht2, g_Pht2);
    cudaGetSymbolAddress((void**)&Plt2, g_Plt2);
    cudaGetSymbolAddress((void**)&Ehi,  g_Ehi);
    cudaGetSymbolAddress((void**)&Elo,  g_Elo);
    cudaGetSymbolAddress((void**)&E2hi, g_E2hi);
    cudaGetSymbolAddress((void**)&E2lo, g_E2lo);
    cudaGetSymbolAddress((void**)&Chi,  g_Chi);
    cudaGetSymbolAddress((void**)&Clo,  g_Clo);
    cudaGetSymbolAddress((void**)&Bbhi, g_Bbhi);
    cudaGetSymbolAddress((void**)&Bblo, g_Bblo);
    cudaGetSymbolAddress((void**)&ABhi, g_ABhi);
    cudaGetSymbolAddress((void**)&ABlo, g_ABlo);
    cudaGetSymbolAddress((void**)&Dshi, g_Dshi);
    cudaGetSymbolAddress((void**)&Dslo, g_Dslo);
    cudaGetSymbolAddress((void**)&Zh,   g_Zh);
    cudaGetSymbolAddress((void**)&Zl,   g_Zl);
    cudaGetSymbolAddress((void**)&Zh2,  g_Zh2);
    cudaGetSymbolAddress((void**)&Zl2,  g_Zl2);
    cudaGetSymbolAddress((void**)&Uh,   g_Uh);
    cudaGetSymbolAddress((void**)&Ul,   g_Ul);

    cudaFuncSetAttribute(scan_persist, cudaFuncAttributeMaxDynamicSharedMemorySize, SM_TOT);
    cudaFuncSetAttribute(gemm_tc, cudaFuncAttributeMaxDynamicSharedMemorySize, TC_TOT);

    const int n2 = DD*DD;
    const int g2 = (n2 + 255)/256;
    dim3 gg1(16, 8, 1), gg2(16, 8, 2);

    build_Y_kernel<<<g2, 256>>>(skew, gamma, dtp, Y_);
    init_EPT<<<g2, 256>>>(E_, P_, T_);
    split_T<<<g2, 256>>>(Y_, Yht, Ylt);

    float* Tin = T_; float* Tout = T2_;
    for (int k = 1; k <= NTAYLOR; k++) {
        gemm_tc<<<gg1, 256, TC_TOT>>>(Tin, Yht, Ylt, Yht, Ylt,
                                      Tout, Tout, E_, P_, nullptr,
                                      nullptr, nullptr, nullptr, nullptr,
                                      1.0f/(float)k, 1.0f/(float)(k+1), 1);
        float* tmp = Tin; Tin = Tout; Tout = tmp;
    }
    split_T<<<g2, 256>>>(E_, Eht, Elt);
    split_T<<<g2, 256>>>(P_, Pht, Plt);

    gemm_tc<<<gg2, 256, TC_TOT>>>(E_, Pht, Plt, Eht, Elt,
                                  T2_, T_, nullptr, nullptr, P_,
                                  Pht2, Plt2, Yht, Ylt, 0.f, 0.f, 2);
    gemm_tc<<<gg2, 256, TC_TOT>>>(T_, Pht2, Plt2, Yht, Ylt,
                                  P_, E_, nullptr, nullptr, T2_,
                                  nullptr, nullptr, nullptr, nullptr, 0.f, 0.f, 3);
    // E_ = A_bar, P_ = phi1
    gemm_small<<<16, 256>>>(Bb_, P_, B_ct);          // Bb_ = phi1 @ B_ct (unscaled)

    // E2 = A_bar^2 ; ABb = A_bar @ Bb
    split_T<<<g2, 256>>>(E_, Pht2, Plt2);
    gemm_tc<<<gg1, 256, TC_TOT>>>(E_, Pht2, Plt2, Pht2, Plt2,
                                  T_, T_, nullptr, nullptr, nullptr,
                                  nullptr, nullptr, nullptr, nullptr, 0.f, 0.f, 0);
    gemm_small<<<16, 256>>>(Y_, E_, Bb_);            // Y_ (reused) = A_bar @ Bb

    split_mat<<<g2, 256>>>(E_, Ehi, Elo, DD, DD, DD, DD, dtp, 0);
    split_mat<<<g2, 256>>>(T_, E2hi, E2lo, DD, DD, DD, DD, dtp, 0);
    split_mat<<<(64*DD + 255)/256, 256>>>(Cm, Chi, Clo, NOBS, DD, 64, DD, dtp, 0);
    split_mat<<<(DD*64 + 255)/256, 256>>>(Bb_, Bbhi, Bblo, DD, UDIM, DD, 64, dtp, 1);
    split_mat<<<(DD*64 + 255)/256, 256>>>(Y_, ABhi, ABlo, DD, UDIM, DD, 64, dtp, 1);
    split_mat<<<(64*64 + 255)/256, 256>>>(Dm, Dshi, Dslo, NOBS, UDIM, 64, 64, dtp, 1);
    split_mat<<<g2, 256>>>(z_dyn, Zh, Zl, BB, DD, BB, DD, dtp, 0);
    split_mat<<<(TT*BB*64 + 255)/256, 256>>>(U, Uh, Ul, TT*BB, UDIM, TT*BB, 64, dtp, 0);

    reset_barrier<<<1, 32>>>();

    float* Zo = (float*)d_out;
    float* Yo = (float*)d_out + (size_t)TT*BB*DD;
    scan_persist<<<NCTA, 256, SM_TOT>>>(Zo, Yo,
                                        Ehi, Elo, E2hi, E2lo, Bbhi, Bblo, ABhi, ABlo,
                                        Chi, Clo, Dshi, Dslo,
                                        Zh, Zl, Zh2, Zl2, Uh, Ul);
}

// round 15
// speedup vs baseline: 1.1580x; 1.1580x over previous
#include <cuda_runtime.h>
#include <cuda_bf16.h>
#include <math.h>
#include <stdint.h>

#define DD   512
#define BB   512
#define TT   256
#define UDIM 32
#define NOBS 50
#define NCTA 144

// ---------------- device scratch ----------------
__device__ float g_Y [DD*DD];
__device__ float g_Y2[DD*DD];
__device__ float g_Y3[DD*DD];
__device__ float g_T [DD*DD];
__device__ float g_T2[DD*DD];
__device__ float g_T3[DD*DD];
__device__ float g_E [DD*DD];
__device__ float g_P [DD*DD];
__device__ float g_Bb[DD*UDIM];

__device__ __nv_bfloat16 g_Yht [DD*DD];
__device__ __nv_bfloat16 g_Ylt [DD*DD];
__device__ __nv_bfloat16 g_Eht [DD*DD];   // Y2 split
__device__ __nv_bfloat16 g_Elt [DD*DD];
__device__ __nv_bfloat16 g_Pht [DD*DD];   // Y4 split
__device__ __nv_bfloat16 g_Plt [DD*DD];

__device__ __nv_bfloat16 g_Ehi [DD*DD];
__device__ __nv_bfloat16 g_Elo [DD*DD];
__device__ __nv_bfloat16 g_Chi [64*DD];
__device__ __nv_bfloat16 g_Clo [64*DD];
__device__ __nv_bfloat16 g_Bbhi[DD*64];
__device__ __nv_bfloat16 g_Bblo[DD*64];
__device__ __nv_bfloat16 g_Dshi[64*64];
__device__ __nv_bfloat16 g_Dslo[64*64];

__device__ __nv_bfloat16 g_Zh[2*BB*DD];
__device__ __nv_bfloat16 g_Zl[2*BB*DD];
__device__ __nv_bfloat16 g_Uh[(size_t)TT*BB*64];
__device__ __nv_bfloat16 g_Ul[(size_t)TT*BB*64];

__device__ __align__(128) unsigned g_cnt[8*32];

// ---------------- helpers ----------------
__device__ __forceinline__ uint32_t smem_u32(const void* p) {
    uint32_t a;
    asm("{ .reg .u64 t; cvta.to.shared.u64 t, %1; cvt.u32.u64 %0, t; }" : "=r"(a) : "l"(p));
    return a;
}
#define SWZ(o) ((o) ^ (((o) >> 3) & 0x70))
#define BARH(id) asm volatile("bar.sync %0, 128;" :: "r"(id) : "memory")

__device__ __forceinline__ void ldmx4(uint32_t r[4], uint32_t addr) {
    asm volatile("ldmatrix.sync.aligned.m8n8.x4.shared.b16 {%0,%1,%2,%3}, [%4];"
        : "=r"(r[0]), "=r"(r[1]), "=r"(r[2]), "=r"(r[3]) : "r"(addr));
}
__device__ __forceinline__ void mma16816(float acc[4], const uint32_t a[4],
                                          uint32_t b0, uint32_t b1) {
    asm volatile("mma.sync.aligned.m16n8k16.row.col.f32.bf16.bf16.f32 "
        "{%0,%1,%2,%3},{%4,%5,%6,%7},{%8,%9},{%0,%1,%2,%3};"
        : "+f"(acc[0]), "+f"(acc[1]), "+f"(acc[2]), "+f"(acc[3])
        : "r"(a[0]), "r"(a[1]), "r"(a[2]), "r"(a[3]), "r"(b0), "r"(b1));
}
__device__ __forceinline__ void split4(float4 v, uint32_t hi_a, uint32_t lo_a) {
    __nv_bfloat162 h0 = __floats2bfloat162_rn(v.x, v.y);
    __nv_bfloat162 h1 = __floats2bfloat162_rn(v.z, v.w);
    __nv_bfloat162 l0 = __floats2bfloat162_rn(v.x - __bfloat162float(h0.x), v.y - __bfloat162float(h0.y));
    __nv_bfloat162 l1 = __floats2bfloat162_rn(v.z - __bfloat162float(h1.x), v.w - __bfloat162float(h1.y));
    uint32_t h0u = *(uint32_t*)&h0, h1u = *(uint32_t*)&h1;
    uint32_t l0u = *(uint32_t*)&l0, l1u = *(uint32_t*)&l1;
    asm volatile("st.shared.v2.b32 [%0], {%1,%2};" :: "r"(hi_a), "r"(h0u), "r"(h1u) : "memory");
    asm volatile("st.shared.v2.b32 [%0], {%1,%2};" :: "r"(lo_a), "r"(l0u), "r"(l1u) : "memory");
}
#define MMA_TRIPLE(accw, ahh, all, bhh, bll) \
    mma16816(accw[0][0], ahh##0, bhh[0], bhh[1]); \
    mma16816(accw[0][1], ahh##0, bhh[2], bhh[3]); \
    mma16816(accw[1][0], ahh##1, bhh[0], bhh[1]); \
    mma16816(accw[1][1], ahh##1, bhh[2], bhh[3]); \
    mma16816(accw[0][0], all##0, bhh[0], bhh[1]); \
    mma16816(accw[0][1], all##0, bhh[2], bhh[3]); \
    mma16816(accw[1][0], all##1, bhh[0], bhh[1]); \
    mma16816(accw[1][1], all##1, bhh[2], bhh[3]); \
    mma16816(accw[0][0], ahh##0, bll[0], bll[1]); \
    mma16816(accw[0][1], ahh##0, bll[2], bll[3]); \
    mma16816(accw[1][0], ahh##1, bll[0], bll[1]); \
    mma16816(accw[1][1], ahh##1, bll[2], bll[3]);

// ---------------- setup elementwise kernels ----------------
__global__ void build_Y_kernel(const float* __restrict__ skew, const float* __restrict__ gamma,
                               const float* __restrict__ dtp, float* __restrict__ Y)
{
    int idx = blockIdx.x*256 + threadIdx.x;
    if (idx >= DD*DD) return;
    int i = idx >> 9, j = idx & (DD-1);
    float v;
    if (i < j)      v =  skew[i*(DD-1) - (i*(i-1))/2 + (j-i-1)];
    else if (i > j) v = -skew[j*(DD-1) - (j*(j-1))/2 + (i-j-1)];
    else { float g = gamma[i]; v = -(fmaxf(g,0.f) + log1pf(expf(-fabsf(g)))); }
    Y[idx] = v * dtp[0];
}
__global__ void reset_barrier() { if (threadIdx.x < 8) g_cnt[threadIdx.x*32] = 0; }

__global__ void split_T(const float* __restrict__ src,
                        __nv_bfloat16* __restrict__ h, __nv_bfloat16* __restrict__ l)
{
    int idx = blockIdx.x*256 + threadIdx.x;
    if (idx >= DD*DD) return;
    int r = idx >> 9, c = idx & (DD-1);
    float v = src[idx];
    __nv_bfloat16 hh = __float2bfloat16(v);
    h[(size_t)c*DD + r] = hh;
    l[(size_t)c*DD + r] = __float2bfloat16(v - __bfloat162float(hh));
}
__global__ void split_mat(const float* __restrict__ src, __nv_bfloat16* hi, __nv_bfloat16* lo,
                          int rs, int cs, int rd, int cd, const float* dtp, int usedt)
{
    int idx = blockIdx.x*256 + threadIdx.x;
    if (idx >= rd*cd) return;
    int r = idx / cd, c = idx % cd;
    float v = (r < rs && c < cs) ? src[(size_t)r*cs + c] : 0.f;
    if (usedt) v *= dtp[0];
    __nv_bfloat16 h = __float2bfloat16(v);
    hi[idx] = h;
    lo[idx] = __float2bfloat16(v - __bfloat162float(h));
}
// HE = c12 I + c13 Y + c14 Y2 + c15 Y3 ; HP = c13 I + c14 Y + c15 Y2 + c16 Y3
__global__ void init_H(const float* __restrict__ Y, const float* __restrict__ Y2,
                       const float* __restrict__ Y3, float* __restrict__ HE, float* __restrict__ HP)
{
    int idx = blockIdx.x*256 + threadIdx.x;
    if (idx >= DD*DD) return;
    float dg = ((idx>>9) == (idx&(DD-1))) ? 1.f : 0.f;
    float y = Y[idx], y2 = Y2[idx], y3 = Y3[idx];
    HE[idx] = 2.0876757e-09f*dg + 1.6059044e-10f*y + 1.1470746e-11f*y2 + 7.6471637e-13f*y3;
    HP[idx] = 1.6059044e-10f*dg + 1.1470746e-11f*y + 7.6471637e-13f*y2 + 4.7794773e-14f*y3;
}

__global__ void gemm_small(float* __restrict__ C, const float* __restrict__ A,
                           const float* __restrict__ Bm)
{
    __shared__ float As[32][33];
    __shared__ float Bs[32][33];
    int tx = threadIdx.x & 15, ty = threadIdx.x >> 4;
    int i0 = blockIdx.x*32;
    float a00=0,a01=0,a10=0,a11=0;
    for (int k0 = 0; k0 < DD; k0 += 32) {
        for (int u = threadIdx.x; u < 32*32; u += 256) {
            int r = u>>5, c = u&31;
            As[r][c] = A[(size_t)(i0+r)*DD + k0+c];
            Bs[r][c] = Bm[(size_t)(k0+r)*UDIM + c];
        }
        __syncthreads();
        #pragma unroll
        for (int k = 0; k < 32; k++) {
            float x0=As[ty*2][k], x1=As[ty*2+1][k];
            float y0=Bs[k][tx*2], y1=Bs[k][tx*2+1];
            a00+=x0*y0; a01+=x0*y1; a10+=x1*y0; a11+=x1*y1;
        }
        __syncthreads();
    }
    C[(size_t)(i0+ty*2+0)*UDIM + tx*2+0]=a00;
    C[(size_t)(i0+ty*2+0)*UDIM + tx*2+1]=a01;
    C[(size_t)(i0+ty*2+1)*UDIM + tx*2+0]=a10;
    C[(size_t)(i0+ty*2+1)*UDIM + tx*2+1]=a11;
}

// ---------------- tensor-core setup GEMM: 256 threads, K-split (R13 body, PS epilogue) ----------------
#define TC_BH  0u
#define TC_BL  32768u
#define TC_ZR  65536u
#define TC_TOT 131072u

__global__ void __launch_bounds__(256) gemm_tc(
    const float* __restrict__ A0, const float* __restrict__ A1,
    const __nv_bfloat16* __restrict__ Bh0, const __nv_bfloat16* __restrict__ Bl0,
    const __nv_bfloat16* __restrict__ Bh1, const __nv_bfloat16* __restrict__ Bl1,
    float* __restrict__ C0, float* __restrict__ C1,
    __nv_bfloat16* __restrict__ Th0, __nv_bfloat16* __restrict__ Tl0,
    __nv_bfloat16* __restrict__ Th1, __nv_bfloat16* __restrict__ Tl1,
    int split0, int split1,
    const float* __restrict__ Yp, const float* __restrict__ Y2p, const float* __restrict__ Y3p,
    float4 cadd0, float4 cadd1, int addmode)
{
    extern __shared__ __align__(1024) char smem[];
    const int tid = threadIdx.x, lane = tid & 31, w = tid >> 5;
    const int half = w >> 2, wsub = w & 3;
    const int wm = (wsub & 1)*32, wn = (wsub >> 1)*16;
    const int htid = tid & 127;
    const int barid = 1 + half;
    const int n0 = blockIdx.x*32, m0 = blockIdx.y*64;
    const int z = blockIdx.z;
    const float* A = z ? A1 : A0;
    const __nv_bfloat16* Bh = z ? Bh1 : Bh0;
    const __nv_bfloat16* Bl = z ? Bl1 : Bl0;
    const uint32_t sb = smem_u32(smem);

    #pragma unroll
    for (int i = 0; i < 8; i++) {
        int idx = i*256 + tid;
        int r = idx >> 6, g = idx & 63;
        uint32_t soff = (uint32_t)((g>>3)*4096) + SWZ((uint32_t)(r*128 + (g&7)*16));
        *(uint4*)(smem + TC_BH + soff) = *(const uint4*)(Bh + (size_t)(n0+r)*DD + g*8);
        *(uint4*)(smem + TC_BL + soff) = *(const uint4*)(Bl + (size_t)(n0+r)*DD + g*8);
    }
    __syncthreads();

    const uint32_t aoff0 = (uint32_t)((wm + 0  + (lane & 15))*128 + ((lane >> 4) << 4));
    const uint32_t aoff1 = (uint32_t)((wm + 16 + (lane & 15))*128 + ((lane >> 4) << 4));
    const uint32_t boff  = (uint32_t)((wn + (lane & 7) + ((lane >> 4) & 1)*8)*128 + ((lane >> 3) & 1)*16);
    const int ldr = htid >> 4, lfq = htid & 15;
    const uint32_t ringb = TC_ZR + (uint32_t)half*32768u;
    const int gs0 = half*4;

    float acc[2][2][4];
    #pragma unroll
    for (int a = 0; a < 2; a++)
        #pragma unroll
        for (int b = 0; b < 2; b++)
            #pragma unroll
            for (int c = 0; c < 4; c++) acc[a][b][c] = 0.f;

    float4 pf[8];
    #pragma unroll
    for (int i = 0; i < 8; i++)
        pf[i] = *(const float4*)(A + (size_t)(m0 + i*8 + ldr)*DD + gs0*64 + lfq*4);
    {
        uint32_t zb = sb + ringb + 16384u;
        #pragma unroll
        for (int i = 0; i < 8; i++) {
            uint32_t off = SWZ((uint32_t)((i*8+ldr)*128 + lfq*8));
            split4(pf[i], zb + off, zb + 8192u + off);
        }
    }
    BARH(barid);

    for (int s = 0; s < 4; s++) {
        int gs = gs0 + s;
        if (s + 1 < 4) {
            #pragma unroll
            for (int i = 0; i < 8; i++)
                pf[i] = *(const float4*)(A + (size_t)(m0 + i*8 + ldr)*DD + (gs+1)*64 + lfq*4);
        }
        {
            uint32_t zb = sb + ringb + (uint32_t)((s+1) & 1)*16384u;
            uint32_t bb = sb + TC_BH + (uint32_t)gs*4096u;
            #pragma unroll
            for (int k16 = 0; k16 < 4; k16++) {
                uint32_t ah0[4], al0[4], ah1[4], al1[4], bh[4], bl[4];
                uint32_t ad0 = zb + SWZ(aoff0 + (uint32_t)k16*32);
                ldmx4(ah0, ad0); ldmx4(al0, ad0 + 8192u);
                uint32_t ad1 = zb + SWZ(aoff1 + (uint32_t)k16*32);
                ldmx4(ah1, ad1); ldmx4(al1, ad1 + 8192u);
                uint32_t bd = bb + SWZ(boff + (uint32_t)k16*32);
                ldmx4(bh, bd); ldmx4(bl, bd + 32768u);
                MMA_TRIPLE(acc, ah, al, bh, bl)
            }
        }
        BARH(barid);
        if (s + 1 < 4) {
            uint32_t zb = sb + ringb + (uint32_t)(s & 1)*16384u;
            #pragma unroll
            for (int i = 0; i < 8; i++) {
                uint32_t off = SWZ((uint32_t)((i*8+ldr)*128 + lfq*8));
                split4(pf[i], zb + off, zb + 8192u + off);
            }
            BARH(barid);
        }
    }

    __syncthreads();
    if (half == 1) {
        uint32_t ra = sb + TC_ZR + 32768u + (uint32_t)htid*64u;
        #pragma unroll
        for (int mi = 0; mi < 2; mi++)
            #pragma unroll
            for (int ni = 0; ni < 2; ni++)
                asm volatile("st.shared.v4.b32 [%0], {%1,%2,%3,%4};"
                    :: "r"(ra + (uint32_t)(mi*2+ni)*16u),
                       "r"(__float_as_uint(acc[mi][ni][0])), "r"(__float_as_uint(acc[mi][ni][1])),
                       "r"(__float_as_uint(acc[mi][ni][2])), "r"(__float_as_uint(acc[mi][ni][3])) : "memory");
    }
    __syncthreads();
    if (half != 0) return;
    {
        const float* red = (const float*)(smem + TC_ZR + 32768u) + htid*16;
        #pragma unroll
        for (int mi = 0; mi < 2; mi++)
            #pragma unroll
            for (int ni = 0; ni < 2; ni++)
                #pragma unroll
                for (int c = 0; c < 4; c++)
                    acc[mi][ni][c] += red[(mi*2+ni)*4 + c];
    }

    int r0 = m0 + wm + (lane >> 2);
    int c0 = n0 + wn + (lane & 3)*2;
    float* Cw = z ? C1 : C0;
    __nv_bfloat16* Th = z ? Th1 : Th0;
    __nv_bfloat16* Tl = z ? Tl1 : Tl0;
    const int dosplit = z ? split1 : split0;
    const float4 ca = z ? cadd1 : cadd0;

    #pragma unroll
    for (int mi = 0; mi < 2; mi++)
        #pragma unroll
        for (int ni = 0; ni < 2; ni++)
            #pragma unroll
            for (int h = 0; h < 2; h++) {
                int rr = r0 + mi*16 + h*8, cc = c0 + ni*8;
                size_t idx = (size_t)rr*DD + cc;
                float v0 = acc[mi][ni][h*2+0];
                float v1 = acc[mi][ni][h*2+1];
                if (addmode) {
                    float2 y  = *(const float2*)(Yp  + idx);
                    float2 y2 = *(const float2*)(Y2p + idx);
                    float2 y3 = *(const float2*)(Y3p + idx);
                    v0 += ca.y*y.x + ca.z*y2.x + ca.w*y3.x + ((rr == cc)   ? ca.x : 0.f);
                    v1 += ca.y*y.y + ca.z*y2.y + ca.w*y3.y + ((rr == cc+1) ? ca.x : 0.f);
                }
                *(float2*)(Cw + idx) = make_float2(v0, v1);
                if (dosplit) {
                    __nv_bfloat16 h0 = __float2bfloat16(v0);
                    __nv_bfloat16 h1 = __float2bfloat16(v1);
                    Th[(size_t)cc*DD + rr]     = h0;
                    Tl[(size_t)cc*DD + rr]     = __float2bfloat16(v0 - __bfloat162float(h0));
                    Th[(size_t)(cc+1)*DD + rr] = h1;
                    Tl[(size_t)(cc+1)*DD + rr] = __float2bfloat16(v1 - __bfloat162float(h1));
                }
            }
}

// ---------------- persistent mma scan (R13/R11 verbatim) ----------------
#define SM_BH   0u
#define SM_BL   32768u
#define SM_B2H  65536u
#define SM_B2L  69632u
#define SM_ZR   73728u
#define SM_RED  73728u
#define SM_TOT  139264u

__device__ __forceinline__ void gb_arrive(int blk) {
    __syncthreads();
    if (threadIdx.x == 0) {
        __threadfence();
        atomicAdd(&g_cnt[(blk & 7)*32], 1u);
    }
}
__device__ __forceinline__ void gb_wait(unsigned want) {
    if (threadIdx.x == 0) {
        unsigned s;
        do {
            s = 0;
            #pragma unroll
            for (int i = 0; i < 8; i++) s += *(volatile unsigned*)&g_cnt[i*32];
        } while (s < want);
        __threadfence();
    }
    __syncthreads();
}

__global__ void __launch_bounds__(256) scan_persist(
    float* __restrict__ Zo, float* __restrict__ Yo,
    const __nv_bfloat16* __restrict__ Ehi,  const __nv_bfloat16* __restrict__ Elo,
    const __nv_bfloat16* __restrict__ Bbhi, const __nv_bfloat16* __restrict__ Bblo,
    const __nv_bfloat16* __restrict__ Chi,  const __nv_bfloat16* __restrict__ Clo,
    const __nv_bfloat16* __restrict__ Dshi, const __nv_bfloat16* __restrict__ Dslo,
    __nv_bfloat16* __restrict__ Zh, __nv_bfloat16* __restrict__ Zl,
    const __nv_bfloat16* __restrict__ Uh, const __nv_bfloat16* __restrict__ Ul)
{
    extern __shared__ __align__(1024) char smem[];
    const int tid  = threadIdx.x;
    const int lane = tid & 31;
    const int w    = tid >> 5;
    const int half = w >> 2;
    const int wsub = w & 3;
    const int wm = (wsub & 1) * 32;
    const int wn = (wsub >> 1) * 16;
    const int htid = tid & 127;
    const int barid = 1 + half;
    const int blk = blockIdx.x;
    const bool isZ = blk < 128;

    int m0, n0;
    const __nv_bfloat16 *Bh_g, *Bl_g, *B2h_g, *B2l_g;
    if (isZ) {
        m0 = (blk >> 4) * 64; n0 = (blk & 15) * 32;
        Bh_g = Ehi; Bl_g = Elo; B2h_g = Bbhi; B2l_g = Bblo;
    } else {
        int local = blk - 128;
        m0 = (local >> 1) * 64; n0 = (local & 1) * 32;
        Bh_g = Chi; Bl_g = Clo; B2h_g = Dshi; B2l_g = Dslo;
    }

    const uint32_t sb = smem_u32(smem);

    #pragma unroll
    for (int i = 0; i < 8; i++) {
        int idx = i*256 + tid;
        int r = idx >> 6, g = idx & 63;
        uint32_t soff = (uint32_t)((g >> 3)*4096) + SWZ((uint32_t)(r*128 + (g & 7)*16));
        *(uint4*)(smem + SM_BH + soff) = *(const uint4*)(Bh_g + (size_t)(n0 + r)*DD + g*8);
        *(uint4*)(smem + SM_BL + soff) = *(const uint4*)(Bl_g + (size_t)(n0 + r)*DD + g*8);
    }
    {
        int r = tid >> 3, g = tid & 7;
        uint32_t soff = SWZ((uint32_t)(r*128 + g*16));
        *(uint4*)(smem + SM_B2H + soff) = *(const uint4*)(B2h_g + (size_t)(n0 + r)*64 + g*8);
        *(uint4*)(smem + SM_B2L + soff) = *(const uint4*)(B2l_g + (size_t)(n0 + r)*64 + g*8);
    }
    __syncthreads();

    const uint32_t aoff0 = (uint32_t)((wm + 0  + (lane & 15))*128 + ((lane >> 4) << 4));
    const uint32_t aoff1 = (uint32_t)((wm + 16 + (lane & 15))*128 + ((lane >> 4) << 4));
    const uint32_t boff  = (uint32_t)((wn + (lane & 7) + ((lane >> 4) & 1)*8)*128 + ((lane >> 3) & 1)*16);
    const int ldr = htid >> 3;
    const int ldg = htid & 7;
    const uint32_t ringb = SM_ZR + (uint32_t)half*32768u;
    const int gs0 = half*4;

    for (int t = 0; t <= TT; t++) {
        const bool active = isZ ? (t < TT) : (t >= 1);
        float acc[2][2][4];
        if (active) {
            #pragma unroll
            for (int a = 0; a < 2; a++)
                #pragma unroll
                for (int b = 0; b < 2; b++)
                    #pragma unroll
                    for (int c = 0; c < 4; c++) acc[a][b][c] = 0.f;

            if (half == 0) {
                int tu = isZ ? t : (t-1);
                const __nv_bfloat16* uh = Uh + (size_t)tu*BB*64;
                const __nv_bfloat16* ul = Ul + (size_t)tu*BB*64;
                #pragma unroll
                for (int i = 0; i < 4; i++) {
                    int r = i*16 + ldr;
                    uint32_t off = SWZ((uint32_t)(r*128 + ldg*16));
                    *(uint4*)(smem + ringb + off)         = *(const uint4*)(uh + (size_t)(m0 + r)*64 + ldg*8);
                    *(uint4*)(smem + ringb + 8192u + off) = *(const uint4*)(ul + (size_t)(m0 + r)*64 + ldg*8);
                }
                BARH(barid);
                uint32_t slot0 = sb + ringb;
                uint32_t bb = sb + SM_B2H;
                #pragma unroll
                for (int k16 = 0; k16 < 4; k16++) {
                    uint32_t ah0[4], al0[4], ah1[4], al1[4], bh[4], bl[4];
                    uint32_t ad0 = slot0 + SWZ(aoff0 + (uint32_t)k16*32);
                    ldmx4(ah0, ad0); ldmx4(al0, ad0 + 8192u);
                    uint32_t ad1 = slot0 + SWZ(aoff1 + (uint32_t)k16*32);
                    ldmx4(ah1, ad1); ldmx4(al1, ad1 + 8192u);
                    uint32_t bd = bb + SWZ(boff + (uint32_t)k16*32);
                    ldmx4(bh, bd); ldmx4(bl, bd + 4096u);
                    MMA_TRIPLE(acc, ah, al, bh, bl)
                }
            }
        }
        if (t > 0) gb_wait((unsigned)NCTA * (unsigned)t);

        if (active) {
            const __nv_bfloat16* zh = Zh + (size_t)(t & 1)*BB*DD;
            const __nv_bfloat16* zl = Zl + (size_t)(t & 1)*BB*DD;
            uint4 ph[4], pl[4];
            #pragma unroll
            for (int i = 0; i < 4; i++) {
                int r = i*16 + ldr;
                ph[i] = *(const uint4*)(zh + (size_t)(m0 + r)*DD + gs0*64 + ldg*8);
                pl[i] = *(const uint4*)(zl + (size_t)(m0 + r)*DD + gs0*64 + ldg*8);
            }
            {
                uint32_t zboff = ringb + 16384u;
                #pragma unroll
                for (int i = 0; i < 4; i++) {
                    int r = i*16 + ldr;
                    uint32_t off = SWZ((uint32_t)(r*128 + ldg*16));
                    *(uint4*)(smem + zboff + off) = ph[i];
                    *(uint4*)(smem + zboff + 8192u + off) = pl[i];
                }
            }
            BARH(barid);

            for (int s = 0; s < 4; s++) {
                int gs = gs0 + s;
                if (s + 1 < 4) {
                    #pragma unroll
                    for (int i = 0; i < 4; i++) {
                        int r = i*16 + ldr;
                        ph[i] = *(const uint4*)(zh + (size_t)(m0 + r)*DD + (gs+1)*64 + ldg*8);
                        pl[i] = *(const uint4*)(zl + (size_t)(m0 + r)*DD + (gs+1)*64 + ldg*8);
                    }
                }
                {
                    uint32_t zb = sb + ringb + (uint32_t)((s+1) & 1)*16384u;
                    uint32_t bb = sb + SM_BH + (uint32_t)gs*4096u;
                    #pragma unroll
                    for (int k16 = 0; k16 < 4; k16++) {
                        uint32_t ah0[4], al0[4], ah1[4], al1[4], bh[4], bl[4];
                        uint32_t ad0 = zb + SWZ(aoff0 + (uint32_t)k16*32);
                        ldmx4(ah0, ad0); ldmx4(al0, ad0 + 8192u);
                        uint32_t ad1 = zb + SWZ(aoff1 + (uint32_t)k16*32);
                        ldmx4(ah1, ad1); ldmx4(al1, ad1 + 8192u);
                        uint32_t bd = bb + SWZ(boff + (uint32_t)k16*32);
                        ldmx4(bh, bd); ldmx4(bl, bd + 32768u);
                        MMA_TRIPLE(acc, ah, al, bh, bl)
                    }
                }
                BARH(barid);
                if (s + 1 < 4) {
                    uint32_t zboff = ringb + (uint32_t)(s & 1)*16384u;
                    #pragma unroll
                    for (int i = 0; i < 4; i++) {
                        int r = i*16 + ldr;
                        uint32_t off = SWZ((uint32_t)(r*128 + ldg*16));
                        *(uint4*)(smem + zboff + off) = ph[i];
                        *(uint4*)(smem + zboff + 8192u + off) = pl[i];
                    }
                    BARH(barid);
                }
            }

            __syncthreads();
            if (half == 1) {
                uint32_t ra = sb + SM_RED + (uint32_t)htid*64u;
                #pragma unroll
                for (int mi = 0; mi < 2; mi++)
                    #pragma unroll
                    for (int ni = 0; ni < 2; ni++) {
                        float4 v = make_float4(acc[mi][ni][0], acc[mi][ni][1],
                                               acc[mi][ni][2], acc[mi][ni][3]);
                        asm volatile("st.shared.v4.b32 [%0], {%1,%2,%3,%4};"
                            :: "r"(ra + (uint32_t)(mi*2+ni)*16u),
                               "r"(__float_as_uint(v.x)), "r"(__float_as_uint(v.y)),
                               "r"(__float_as_uint(v.z)), "r"(__float_as_uint(v.w)) : "memory");
                    }
            }
            __syncthreads();
            if (half == 0) {
                const float* red = (const float*)(smem + SM_RED) + htid*16;
                #pragma unroll
                for (int mi = 0; mi < 2; mi++)
                    #pragma unroll
                    for (int ni = 0; ni < 2; ni++)
                        #pragma unroll
                        for (int c = 0; c < 4; c++)
                            acc[mi][ni][c] += red[(mi*2+ni)*4 + c];

                int r0 = m0 + wm + (lane >> 2);
                int c0 = n0 + wn + (lane & 3)*2;
                if (isZ) {
                    float* Zout = Zo + (size_t)t*BB*DD;
                    __nv_bfloat16* zhn = Zh + (size_t)((t+1) & 1)*BB*DD;
                    __nv_bfloat16* zln = Zl + (size_t)((t+1) & 1)*BB*DD;
                    #pragma unroll
                    for (int mi = 0; mi < 2; mi++)
                        #pragma unroll
                        for (int ni = 0; ni < 2; ni++) {
                            int row = r0 + mi*16, col = c0 + ni*8;
                            float a0 = acc[mi][ni][0], a1 = acc[mi][ni][1];
                            float a2 = acc[mi][ni][2], a3 = acc[mi][ni][3];
                            *(float2*)(Zout + (size_t)row*DD + col)     = make_float2(a0, a1);
                            *(float2*)(Zout + (size_t)(row+8)*DD + col) = make_float2(a2, a3);
                            __nv_bfloat162 h0 = __floats2bfloat162_rn(a0, a1);
                            __nv_bfloat162 l0 = __floats2bfloat162_rn(a0 - __bfloat162float(h0.x),
                                                                      a1 - __bfloat162float(h0.y));
                            __nv_bfloat162 h1 = __floats2bfloat162_rn(a2, a3);
                            __nv_bfloat162 l1 = __floats2bfloat162_rn(a2 - __bfloat162float(h1.x),
                                                                      a3 - __bfloat162float(h1.y));
                            *(__nv_bfloat162*)(zhn + (size_t)row*DD + col)     = h0;
                            *(__nv_bfloat162*)(zln + (size_t)row*DD + col)     = l0;
                            *(__nv_bfloat162*)(zhn + (size_t)(row+8)*DD + col) = h1;
                            *(__nv_bfloat162*)(zln + (size_t)(row+8)*DD + col) = l1;
                        }
                } else {
                    float* Yout = Yo + (size_t)(t-1)*BB*NOBS;
                    #pragma unroll
                    for (int mi = 0; mi < 2; mi++)
                        #pragma unroll
                        for (int ni = 0; ni < 2; ni++) {
                            int row = r0 + mi*16, col = c0 + ni*8;
                            if (col < NOBS)     Yout[(size_t)row*NOBS + col]       = acc[mi][ni][0];
                            if (col + 1 < NOBS) Yout[(size_t)row*NOBS + col + 1]   = acc[mi][ni][1];
                            if (col < NOBS)     Yout[(size_t)(row+8)*NOBS + col]   = acc[mi][ni][2];
                            if (col + 1 < NOBS) Yout[(size_t)(row+8)*NOBS + col+1] = acc[mi][ni][3];
                        }
                }
            }
        }
        if (t < TT) gb_arrive(blk);
    }
}

// ---------------- host orchestration ----------------
extern "C" void kernel_launch(void* const* d_in, const int* in_sizes, int n_in,
                              void* d_out, int out_size)
{
    const float* z_dyn = (const float*)d_in[0];
    const float* dtp   = (const float*)d_in[2];
    const float* U     = (const float*)d_in[3];
    const float* skew  = (const float*)d_in[4];
    const float* gamma = (const float*)d_in[5];
    const float* B_ct  = (const float*)d_in[6];
    const float* Cm    = (const float*)d_in[7];
    const float* Dm    = (const float*)d_in[8];

    float *Y_, *Y2_, *Y3_, *T_, *T2_, *T3_, *E_, *P_, *Bb_;
    cudaGetSymbolAddress((void**)&Y_,  g_Y);
    cudaGetSymbolAddress((void**)&Y2_, g_Y2);
    cudaGetSymbolAddress((void**)&Y3_, g_Y3);
    cudaGetSymbolAddress((void**)&T_,  g_T);
    cudaGetSymbolAddress((void**)&T2_, g_T2);
    cudaGetSymbolAddress((void**)&T3_, g_T3);
    cudaGetSymbolAddress((void**)&E_,  g_E);
    cudaGetSymbolAddress((void**)&P_,  g_P);
    cudaGetSymbolAddress((void**)&Bb_, g_Bb);

    __nv_bfloat16 *Yht, *Ylt, *Eht, *Elt, *Pht, *Plt;
    __nv_bfloat16 *Ehi, *Elo, *Chi, *Clo, *Bbhi, *Bblo, *Dshi, *Dslo, *Zh, *Zl, *Uh, *Ul;
    cudaGetSymbolAddress((void**)&Yht,  g_Yht);
    cudaGetSymbolAddress((void**)&Ylt,  g_Ylt);
    cudaGetSymbolAddress((void**)&Eht,  g_Eht);
    cudaGetSymbolAddress((void**)&Elt,  g_Elt);
    cudaGetSymbolAddress((void**)&Pht,  g_Pht);
    cudaGetSymbolAddress((void**)&Plt,  g_Plt);
    cudaGetSymbolAddress((void**)&Ehi,  g_Ehi);
    cudaGetSymbolAddress((void**)&Elo,  g_Elo);
    cudaGetSymbolAddress((void**)&Chi,  g_Chi);
    cudaGetSymbolAddress((void**)&Clo,  g_Clo);
    cudaGetSymbolAddress((void**)&Bbhi, g_Bbhi);
    cudaGetSymbolAddress((void**)&Bblo, g_Bblo);
    cudaGetSymbolAddress((void**)&Dshi, g_Dshi);
    cudaGetSymbolAddress((void**)&Dslo, g_Dslo);
    cudaGetSymbolAddress((void**)&Zh,   g_Zh);
    cudaGetSymbolAddress((void**)&Zl,   g_Zl);
    cudaGetSymbolAddress((void**)&Uh,   g_Uh);
    cudaGetSymbolAddress((void**)&Ul,   g_Ul);

    cudaFuncSetAttribute(scan_persist, cudaFuncAttributeMaxDynamicSharedMemorySize, SM_TOT);
    cudaFuncSetAttribute(gemm_tc, cudaFuncAttributeMaxDynamicSharedMemorySize, TC_TOT);

    const int n2 = DD*DD;
    const int g2 = (n2 + 255)/256;
    dim3 gg1(16, 8, 1), gg2(16, 8, 2);
    const float4 z4  = make_float4(0.f, 0.f, 0.f, 0.f);
    const float4 D2E = make_float4(2.4801587e-05f, 2.7557319e-06f, 2.7557319e-07f, 2.5052108e-08f);
    const float4 D1E = make_float4(4.1666667e-02f, 8.3333333e-03f, 1.3888889e-03f, 1.9841270e-04f);
    const float4 D0E = make_float4(1.f, 1.f, 0.5f, 1.6666667e-01f);
    const float4 D2P = make_float4(2.7557319e-06f, 2.7557319e-07f, 2.5052108e-08f, 2.0876757e-09f);
    const float4 D1P = make_float4(8.3333333e-03f, 1.3888889e-03f, 1.9841270e-04f, 2.4801587e-05f);
    const float4 D0P = make_float4(1.f, 0.5f, 1.6666667e-01f, 4.1666667e-02f);

    // Y = A*dt ; PS-16 for E=expm(Y), P=phi1(Y)
    build_Y_kernel<<<g2, 256>>>(skew, gamma, dtp, Y_);
    split_T<<<g2, 256>>>(Y_, Yht, Ylt);

    // Y2 = Y@Y (split -> Eht/Elt)
    gemm_tc<<<gg1, 256, TC_TOT>>>(Y_, Y_, Yht, Ylt, Yht, Ylt, Y2_, Y2_,
                                  Eht, Elt, Eht, Elt, 1, 0,
                                  Y_, Y2_, Y3_, z4, z4, 0);
    // z0: Y3 = Y2@Y ; z1: Y4(T_) = Y2@Y2 (split -> Pht/Plt)
    gemm_tc<<<gg2, 256, TC_TOT>>>(Y2_, Y2_, Yht, Ylt, Eht, Elt, Y3_, T_,
                                  Pht, Plt, Pht, Plt, 0, 1,
                                  Y_, Y2_, Y3_, z4, z4, 0);
    // H init (degree-3 top blocks)
    init_H<<<g2, 256>>>(Y_, Y2_, Y3_, E_, P_);
    // Horner x3: H <- H@Y4 + D_q
    gemm_tc<<<gg2, 256, TC_TOT>>>(E_, P_, Pht, Plt, Pht, Plt, T2_, T3_,
                                  Pht, Plt, Pht, Plt, 0, 0,
                                  Y_, Y2_, Y3_, D2E, D2P, 1);
    gemm_tc<<<gg2, 256, TC_TOT>>>(T2_, T3_, Pht, Plt, Pht, Plt, E_, P_,
                                  Pht, Plt, Pht, Plt, 0, 0,
                                  Y_, Y2_, Y3_, D1E, D1P, 1);
    gemm_tc<<<gg2, 256, TC_TOT>>>(E_, P_, Pht, Plt, Pht, Plt, T2_, T3_,
                                  Pht, Plt, Pht, Plt, 0, 0,
                                  Y_, Y2_, Y3_, D0E, D0P, 1);
    // E = T2_, P = T3_
    gemm_small<<<16, 256>>>(Bb_, T3_, B_ct);   // Bb = phi1 @ B_ct (dt applied in split)

    split_mat<<<g2, 256>>>(T2_, Ehi, Elo, DD, DD, DD, DD, dtp, 0);
    split_mat<<<(64*DD + 255)/256, 256>>>(Cm, Chi, Clo, NOBS, DD, 64, DD, dtp, 0);
    split_mat<<<(DD*64 + 255)/256, 256>>>(Bb_, Bbhi, Bblo, DD, UDIM, DD, 64, dtp, 1);
    split_mat<<<(64*64 + 255)/256, 256>>>(Dm, Dshi, Dslo, NOBS, UDIM, 64, 64, dtp, 1);
    split_mat<<<g2, 256>>>(z_dyn, Zh, Zl, BB, DD, BB, DD, dtp, 0);
    split_mat<<<(TT*BB*64 + 255)/256, 256>>>(U, Uh, Ul, TT*BB, UDIM, TT*BB, 64, dtp, 0);

    reset_barrier<<<1, 32>>>();

    float* Zo = (float*)d_out;
    float* Yo = (float*)d_out + (size_t)TT*BB*DD;
    scan_persist<<<NCTA, 256, SM_TOT>>>(Zo, Yo,
                                        Ehi, Elo, Bbhi, Bblo, Chi, Clo, Dshi, Dslo,
                                        Zh, Zl, Uh, Ul);
}

// round 16
// speedup vs baseline: 1.2938x; 1.1173x over previous
#include <cuda_runtime.h>
#include <cuda_bf16.h>
#include <math.h>
#include <stdint.h>

#define DD   512
#define BB   512
#define TT   256
#define UDIM 32
#define NOBS 50
#define NCTA 144

// ---------------- device scratch ----------------
__device__ float g_Y [DD*DD];
__device__ float g_Y2[DD*DD];
__device__ float g_Y3[DD*DD];
__device__ float g_T [DD*DD];
__device__ float g_T2[DD*DD];
__device__ float g_T3[DD*DD];
__device__ float g_E [DD*DD];
__device__ float g_P [DD*DD];
__device__ float g_Bb[DD*UDIM];

__device__ __nv_bfloat16 g_Yht [DD*DD];
__device__ __nv_bfloat16 g_Ylt [DD*DD];
__device__ __nv_bfloat16 g_Eht [DD*DD];   // Y2 split
__device__ __nv_bfloat16 g_Elt [DD*DD];
__device__ __nv_bfloat16 g_Pht [DD*DD];   // Y4 split
__device__ __nv_bfloat16 g_Plt [DD*DD];

__device__ __nv_bfloat16 g_Ehi [DD*DD];
__device__ __nv_bfloat16 g_Elo [DD*DD];
__device__ __nv_bfloat16 g_Chi [64*DD];
__device__ __nv_bfloat16 g_Clo [64*DD];
__device__ __nv_bfloat16 g_Bbhi[DD*64];
__device__ __nv_bfloat16 g_Bblo[DD*64];
__device__ __nv_bfloat16 g_Dshi[64*64];
__device__ __nv_bfloat16 g_Dslo[64*64];

__device__ __nv_bfloat16 g_Zh[2*BB*DD];
__device__ __nv_bfloat16 g_Zl[2*BB*DD];
__device__ __nv_bfloat16 g_Uh[(size_t)TT*BB*64];
__device__ __nv_bfloat16 g_Ul[(size_t)TT*BB*64];

__device__ __align__(128) unsigned g_cnt[8*32];

// ---------------- helpers ----------------
__device__ __forceinline__ uint32_t smem_u32(const void* p) {
    uint32_t a;
    asm("{ .reg .u64 t; cvta.to.shared.u64 t, %1; cvt.u32.u64 %0, t; }" : "=r"(a) : "l"(p));
    return a;
}
#define SWZ(o) ((o) ^ (((o) >> 3) & 0x70))
#define BARH(id) asm volatile("bar.sync %0, 128;" :: "r"(id) : "memory")

__device__ __forceinline__ void ldmx4(uint32_t r[4], uint32_t addr) {
    asm volatile("ldmatrix.sync.aligned.m8n8.x4.shared.b16 {%0,%1,%2,%3}, [%4];"
        : "=r"(r[0]), "=r"(r[1]), "=r"(r[2]), "=r"(r[3]) : "r"(addr));
}
__device__ __forceinline__ void mma16816(float acc[4], const uint32_t a[4],
                                          uint32_t b0, uint32_t b1) {
    asm volatile("mma.sync.aligned.m16n8k16.row.col.f32.bf16.bf16.f32 "
        "{%0,%1,%2,%3},{%4,%5,%6,%7},{%8,%9},{%0,%1,%2,%3};"
        : "+f"(acc[0]), "+f"(acc[1]), "+f"(acc[2]), "+f"(acc[3])
        : "r"(a[0]), "r"(a[1]), "r"(a[2]), "r"(a[3]), "r"(b0), "r"(b1));
}
__device__ __forceinline__ void split4(float4 v, uint32_t hi_a, uint32_t lo_a) {
    __nv_bfloat162 h0 = __floats2bfloat162_rn(v.x, v.y);
    __nv_bfloat162 h1 = __floats2bfloat162_rn(v.z, v.w);
    __nv_bfloat162 l0 = __floats2bfloat162_rn(v.x - __bfloat162float(h0.x), v.y - __bfloat162float(h0.y));
    __nv_bfloat162 l1 = __floats2bfloat162_rn(v.z - __bfloat162float(h1.x), v.w - __bfloat162float(h1.y));
    uint32_t h0u = *(uint32_t*)&h0, h1u = *(uint32_t*)&h1;
    uint32_t l0u = *(uint32_t*)&l0, l1u = *(uint32_t*)&l1;
    asm volatile("st.shared.v2.b32 [%0], {%1,%2};" :: "r"(hi_a), "r"(h0u), "r"(h1u) : "memory");
    asm volatile("st.shared.v2.b32 [%0], {%1,%2};" :: "r"(lo_a), "r"(l0u), "r"(l1u) : "memory");
}
#define MMA_TRIPLE(accw, ahh, all, bhh, bll) \
    mma16816(accw[0][0], ahh##0, bhh[0], bhh[1]); \
    mma16816(accw[0][1], ahh##0, bhh[2], bhh[3]); \
    mma16816(accw[1][0], ahh##1, bhh[0], bhh[1]); \
    mma16816(accw[1][1], ahh##1, bhh[2], bhh[3]); \
    mma16816(accw[0][0], all##0, bhh[0], bhh[1]); \
    mma16816(accw[0][1], all##0, bhh[2], bhh[3]); \
    mma16816(accw[1][0], all##1, bhh[0], bhh[1]); \
    mma16816(accw[1][1], all##1, bhh[2], bhh[3]); \
    mma16816(accw[0][0], ahh##0, bll[0], bll[1]); \
    mma16816(accw[0][1], ahh##0, bll[2], bll[3]); \
    mma16816(accw[1][0], ahh##1, bll[0], bll[1]); \
    mma16816(accw[1][1], ahh##1, bll[2], bll[3]);

// 12-MMA triple for M16xN32 warp tile (single A frag, two B frag pairs)
#define MMA_TRIPLE32(accw, ah, al, bh0, bh1, bl0, bl1) \
    mma16816(accw[0], ah, bh0[0], bh0[1]); \
    mma16816(accw[1], ah, bh0[2], bh0[3]); \
    mma16816(accw[2], ah, bh1[0], bh1[1]); \
    mma16816(accw[3], ah, bh1[2], bh1[3]); \
    mma16816(accw[0], al, bh0[0], bh0[1]); \
    mma16816(accw[1], al, bh0[2], bh0[3]); \
    mma16816(accw[2], al, bh1[0], bh1[1]); \
    mma16816(accw[3], al, bh1[2], bh1[3]); \
    mma16816(accw[0], ah, bl0[0], bl0[1]); \
    mma16816(accw[1], ah, bl0[2], bl0[3]); \
    mma16816(accw[2], ah, bl1[0], bl1[1]); \
    mma16816(accw[3], ah, bl1[2], bl1[3]);

// ---------------- setup elementwise kernels (R15 verbatim) ----------------
__global__ void build_Y_kernel(const float* __restrict__ skew, const float* __restrict__ gamma,
                               const float* __restrict__ dtp, float* __restrict__ Y)
{
    int idx = blockIdx.x*256 + threadIdx.x;
    if (idx >= DD*DD) return;
    int i = idx >> 9, j = idx & (DD-1);
    float v;
    if (i < j)      v =  skew[i*(DD-1) - (i*(i-1))/2 + (j-i-1)];
    else if (i > j) v = -skew[j*(DD-1) - (j*(j-1))/2 + (i-j-1)];
    else { float g = gamma[i]; v = -(fmaxf(g,0.f) + log1pf(expf(-fabsf(g)))); }
    Y[idx] = v * dtp[0];
}
__global__ void reset_barrier() { if (threadIdx.x < 8) g_cnt[threadIdx.x*32] = 0; }

__global__ void split_T(const float* __restrict__ src,
                        __nv_bfloat16* __restrict__ h, __nv_bfloat16* __restrict__ l)
{
    int idx = blockIdx.x*256 + threadIdx.x;
    if (idx >= DD*DD) return;
    int r = idx >> 9, c = idx & (DD-1);
    float v = src[idx];
    __nv_bfloat16 hh = __float2bfloat16(v);
    h[(size_t)c*DD + r] = hh;
    l[(size_t)c*DD + r] = __float2bfloat16(v - __bfloat162float(hh));
}
__global__ void split_mat(const float* __restrict__ src, __nv_bfloat16* hi, __nv_bfloat16* lo,
                          int rs, int cs, int rd, int cd, const float* dtp, int usedt)
{
    int idx = blockIdx.x*256 + threadIdx.x;
    if (idx >= rd*cd) return;
    int r = idx / cd, c = idx % cd;
    float v = (r < rs && c < cs) ? src[(size_t)r*cs + c] : 0.f;
    if (usedt) v *= dtp[0];
    __nv_bfloat16 h = __float2bfloat16(v);
    hi[idx] = h;
    lo[idx] = __float2bfloat16(v - __bfloat162float(h));
}
__global__ void init_H(const float* __restrict__ Y, const float* __restrict__ Y2,
                       const float* __restrict__ Y3, float* __restrict__ HE, float* __restrict__ HP)
{
    int idx = blockIdx.x*256 + threadIdx.x;
    if (idx >= DD*DD) return;
    float dg = ((idx>>9) == (idx&(DD-1))) ? 1.f : 0.f;
    float y = Y[idx], y2 = Y2[idx], y3 = Y3[idx];
    HE[idx] = 2.0876757e-09f*dg + 1.6059044e-10f*y + 1.1470746e-11f*y2 + 7.6471637e-13f*y3;
    HP[idx] = 1.6059044e-10f*dg + 1.1470746e-11f*y + 7.6471637e-13f*y2 + 4.7794773e-14f*y3;
}
__global__ void gemm_small(float* __restrict__ C, const float* __restrict__ A,
                           const float* __restrict__ Bm)
{
    __shared__ float As[32][33];
    __shared__ float Bs[32][33];
    int tx = threadIdx.x & 15, ty = threadIdx.x >> 4;
    int i0 = blockIdx.x*32;
    float a00=0,a01=0,a10=0,a11=0;
    for (int k0 = 0; k0 < DD; k0 += 32) {
        for (int u = threadIdx.x; u < 32*32; u += 256) {
            int r = u>>5, c = u&31;
            As[r][c] = A[(size_t)(i0+r)*DD + k0+c];
            Bs[r][c] = Bm[(size_t)(k0+r)*UDIM + c];
        }
        __syncthreads();
        #pragma unroll
        for (int k = 0; k < 32; k++) {
            float x0=As[ty*2][k], x1=As[ty*2+1][k];
            float y0=Bs[k][tx*2], y1=Bs[k][tx*2+1];
            a00+=x0*y0; a01+=x0*y1; a10+=x1*y0; a11+=x1*y1;
        }
        __syncthreads();
    }
    C[(size_t)(i0+ty*2+0)*UDIM + tx*2+0]=a00;
    C[(size_t)(i0+ty*2+0)*UDIM + tx*2+1]=a01;
    C[(size_t)(i0+ty*2+1)*UDIM + tx*2+0]=a10;
    C[(size_t)(i0+ty*2+1)*UDIM + tx*2+1]=a11;
}

// ---------------- tensor-core setup GEMM (R15 verbatim) ----------------
#define TC_BH  0u
#define TC_BL  32768u
#define TC_ZR  65536u
#define TC_TOT 131072u

__global__ void __launch_bounds__(256) gemm_tc(
    const float* __restrict__ A0, const float* __restrict__ A1,
    const __nv_bfloat16* __restrict__ Bh0, const __nv_bfloat16* __restrict__ Bl0,
    const __nv_bfloat16* __restrict__ Bh1, const __nv_bfloat16* __restrict__ Bl1,
    float* __restrict__ C0, float* __restrict__ C1,
    __nv_bfloat16* __restrict__ Th0, __nv_bfloat16* __restrict__ Tl0,
    __nv_bfloat16* __restrict__ Th1, __nv_bfloat16* __restrict__ Tl1,
    int split0, int split1,
    const float* __restrict__ Yp, const float* __restrict__ Y2p, const float* __restrict__ Y3p,
    float4 cadd0, float4 cadd1, int addmode)
{
    extern __shared__ __align__(1024) char smem[];
    const int tid = threadIdx.x, lane = tid & 31, w = tid >> 5;
    const int half = w >> 2, wsub = w & 3;
    const int wm = (wsub & 1)*32, wn = (wsub >> 1)*16;
    const int htid = tid & 127;
    const int barid = 1 + half;
    const int n0 = blockIdx.x*32, m0 = blockIdx.y*64;
    const int z = blockIdx.z;
    const float* A = z ? A1 : A0;
    const __nv_bfloat16* Bh = z ? Bh1 : Bh0;
    const __nv_bfloat16* Bl = z ? Bl1 : Bl0;
    const uint32_t sb = smem_u32(smem);

    #pragma unroll
    for (int i = 0; i < 8; i++) {
        int idx = i*256 + tid;
        int r = idx >> 6, g = idx & 63;
        uint32_t soff = (uint32_t)((g>>3)*4096) + SWZ((uint32_t)(r*128 + (g&7)*16));
        *(uint4*)(smem + TC_BH + soff) = *(const uint4*)(Bh + (size_t)(n0+r)*DD + g*8);
        *(uint4*)(smem + TC_BL + soff) = *(const uint4*)(Bl + (size_t)(n0+r)*DD + g*8);
    }
    __syncthreads();

    const uint32_t aoff0 = (uint32_t)((wm + 0  + (lane & 15))*128 + ((lane >> 4) << 4));
    const uint32_t aoff1 = (uint32_t)((wm + 16 + (lane & 15))*128 + ((lane >> 4) << 4));
    const uint32_t boff  = (uint32_t)((wn + (lane & 7) + ((lane >> 4) & 1)*8)*128 + ((lane >> 3) & 1)*16);
    const int ldr = htid >> 4, lfq = htid & 15;
    const uint32_t ringb = TC_ZR + (uint32_t)half*32768u;
    const int gs0 = half*4;

    float acc[2][2][4];
    #pragma unroll
    for (int a = 0; a < 2; a++)
        #pragma unroll
        for (int b = 0; b < 2; b++)
            #pragma unroll
            for (int c = 0; c < 4; c++) acc[a][b][c] = 0.f;

    float4 pf[8];
    #pragma unroll
    for (int i = 0; i < 8; i++)
        pf[i] = *(const float4*)(A + (size_t)(m0 + i*8 + ldr)*DD + gs0*64 + lfq*4);
    {
        uint32_t zb = sb + ringb + 16384u;
        #pragma unroll
        for (int i = 0; i < 8; i++) {
            uint32_t off = SWZ((uint32_t)((i*8+ldr)*128 + lfq*8));
            split4(pf[i], zb + off, zb + 8192u + off);
        }
    }
    BARH(barid);

    for (int s = 0; s < 4; s++) {
        int gs = gs0 + s;
        if (s + 1 < 4) {
            #pragma unroll
            for (int i = 0; i < 8; i++)
                pf[i] = *(const float4*)(A + (size_t)(m0 + i*8 + ldr)*DD + (gs+1)*64 + lfq*4);
        }
        {
            uint32_t zb = sb + ringb + (uint32_t)((s+1) & 1)*16384u;
            uint32_t bb = sb + TC_BH + (uint32_t)gs*4096u;
            #pragma unroll
            for (int k16 = 0; k16 < 4; k16++) {
                uint32_t ah0[4], al0[4], ah1[4], al1[4], bh[4], bl[4];
                uint32_t ad0 = zb + SWZ(aoff0 + (uint32_t)k16*32);
                ldmx4(ah0, ad0); ldmx4(al0, ad0 + 8192u);
                uint32_t ad1 = zb + SWZ(aoff1 + (uint32_t)k16*32);
                ldmx4(ah1, ad1); ldmx4(al1, ad1 + 8192u);
                uint32_t bd = bb + SWZ(boff + (uint32_t)k16*32);
                ldmx4(bh, bd); ldmx4(bl, bd + 32768u);
                MMA_TRIPLE(acc, ah, al, bh, bl)
            }
        }
        BARH(barid);
        if (s + 1 < 4) {
            uint32_t zb = sb + ringb + (uint32_t)(s & 1)*16384u;
            #pragma unroll
            for (int i = 0; i < 8; i++) {
                uint32_t off = SWZ((uint32_t)((i*8+ldr)*128 + lfq*8));
                split4(pf[i], zb + off, zb + 8192u + off);
            }
            BARH(barid);
        }
    }

    __syncthreads();
    if (half == 1) {
        uint32_t ra = sb + TC_ZR + 32768u + (uint32_t)htid*64u;
        #pragma unroll
        for (int mi = 0; mi < 2; mi++)
            #pragma unroll
            for (int ni = 0; ni < 2; ni++)
                asm volatile("st.shared.v4.b32 [%0], {%1,%2,%3,%4};"
                    :: "r"(ra + (uint32_t)(mi*2+ni)*16u),
                       "r"(__float_as_uint(acc[mi][ni][0])), "r"(__float_as_uint(acc[mi][ni][1])),
                       "r"(__float_as_uint(acc[mi][ni][2])), "r"(__float_as_uint(acc[mi][ni][3])) : "memory");
    }
    __syncthreads();
    if (half != 0) return;
    {
        const float* red = (const float*)(smem + TC_ZR + 32768u) + htid*16;
        #pragma unroll
        for (int mi = 0; mi < 2; mi++)
            #pragma unroll
            for (int ni = 0; ni < 2; ni++)
                #pragma unroll
                for (int c = 0; c < 4; c++)
                    acc[mi][ni][c] += red[(mi*2+ni)*4 + c];
    }

    int r0 = m0 + wm + (lane >> 2);
    int c0 = n0 + wn + (lane & 3)*2;
    float* Cw = z ? C1 : C0;
    __nv_bfloat16* Th = z ? Th1 : Th0;
    __nv_bfloat16* Tl = z ? Tl1 : Tl0;
    const int dosplit = z ? split1 : split0;
    const float4 ca = z ? cadd1 : cadd0;

    #pragma unroll
    for (int mi = 0; mi < 2; mi++)
        #pragma unroll
        for (int ni = 0; ni < 2; ni++)
            #pragma unroll
            for (int h = 0; h < 2; h++) {
                int rr = r0 + mi*16 + h*8, cc = c0 + ni*8;
                size_t idx = (size_t)rr*DD + cc;
                float v0 = acc[mi][ni][h*2+0];
                float v1 = acc[mi][ni][h*2+1];
                if (addmode) {
                    float2 y  = *(const float2*)(Yp  + idx);
                    float2 y2 = *(const float2*)(Y2p + idx);
                    float2 y3 = *(const float2*)(Y3p + idx);
                    v0 += ca.y*y.x + ca.z*y2.x + ca.w*y3.x + ((rr == cc)   ? ca.x : 0.f);
                    v1 += ca.y*y.y + ca.z*y2.y + ca.w*y3.y + ((rr == cc+1) ? ca.x : 0.f);
                }
                *(float2*)(Cw + idx) = make_float2(v0, v1);
                if (dosplit) {
                    __nv_bfloat16 h0 = __float2bfloat16(v0);
                    __nv_bfloat16 h1 = __float2bfloat16(v1);
                    Th[(size_t)cc*DD + rr]     = h0;
                    Tl[(size_t)cc*DD + rr]     = __float2bfloat16(v0 - __bfloat162float(h0));
                    Th[(size_t)(cc+1)*DD + rr] = h1;
                    Tl[(size_t)(cc+1)*DD + rr] = __float2bfloat16(v1 - __bfloat162float(h1));
                }
            }
}

// ---------------- persistent mma scan: M32 x N64 tiles ----------------
// smem: Bop hi 64K | Bop lo 64K | B2 hi 8K | B2 lo 8K | ustage 8K | ring 2x2x8K | red 8K
#define SM_BH   0u
#define SM_BL   65536u
#define SM_B2H  131072u
#define SM_B2L  139264u
#define SM_UST  147456u
#define SM_RING 155648u
#define SM_RED  188416u
#define SM_TOT  196608u

__device__ __forceinline__ void gb_arrive(int blk) {
    __syncthreads();
    if (threadIdx.x == 0) {
        __threadfence();
        atomicAdd(&g_cnt[(blk & 7)*32], 1u);
    }
}
__device__ __forceinline__ void gb_wait(unsigned want) {
    if (threadIdx.x == 0) {
        unsigned s;
        do {
            s = 0;
            #pragma unroll
            for (int i = 0; i < 8; i++) s += *(volatile unsigned*)&g_cnt[i*32];
        } while (s < want);
        __threadfence();
    }
    __syncthreads();
}

__global__ void __launch_bounds__(256) scan_persist(
    float* __restrict__ Zo, float* __restrict__ Yo,
    const __nv_bfloat16* __restrict__ Ehi,  const __nv_bfloat16* __restrict__ Elo,
    const __nv_bfloat16* __restrict__ Bbhi, const __nv_bfloat16* __restrict__ Bblo,
    const __nv_bfloat16* __restrict__ Chi,  const __nv_bfloat16* __restrict__ Clo,
    const __nv_bfloat16* __restrict__ Dshi, const __nv_bfloat16* __restrict__ Dslo,
    __nv_bfloat16* __restrict__ Zh, __nv_bfloat16* __restrict__ Zl,
    const __nv_bfloat16* __restrict__ Uh, const __nv_bfloat16* __restrict__ Ul)
{
    extern __shared__ __align__(1024) char smem[];
    const int tid  = threadIdx.x;
    const int lane = tid & 31;
    const int w    = tid >> 5;
    const int half = w >> 2;
    const int wsub = w & 3;
    const int wm = (wsub & 1) * 16;       // 0 or 16  (M position)
    const int wn = (wsub >> 1) * 32;      // 0 or 32  (N position)
    const int htid = tid & 127;
    const int barid = 1 + half;
    const int blk = blockIdx.x;
    const bool isZ = blk < 128;

    int m0, n0;
    const __nv_bfloat16 *Bh_g, *Bl_g, *B2h_g, *B2l_g;
    if (isZ) {
        m0 = (blk >> 3) * 32; n0 = (blk & 7) * 64;
        Bh_g = Ehi; Bl_g = Elo; B2h_g = Bbhi; B2l_g = Bblo;
    } else {
        int local = blk - 128;
        m0 = local * 32; n0 = 0;
        Bh_g = Chi; Bl_g = Clo; B2h_g = Dshi; B2l_g = Dslo;
    }

    const uint32_t sb = smem_u32(smem);

    // resident B operand: 64 rows x 512 k -> 8 chunks of (64 rows x 64 k)
    #pragma unroll
    for (int i = 0; i < 16; i++) {
        int idx = i*256 + tid;
        int r = idx >> 6, g = idx & 63;
        uint32_t soff = (uint32_t)((g >> 3)*8192) + SWZ((uint32_t)(r*128 + (g & 7)*16));
        *(uint4*)(smem + SM_BH + soff) = *(const uint4*)(Bh_g + (size_t)(n0 + r)*DD + g*8);
        *(uint4*)(smem + SM_BL + soff) = *(const uint4*)(Bl_g + (size_t)(n0 + r)*DD + g*8);
    }
    // B2: 64 rows x 64 k
    #pragma unroll
    for (int i = 0; i < 2; i++) {
        int idx = i*256 + tid;
        int r = idx >> 3, g = idx & 7;
        uint32_t soff = SWZ((uint32_t)(r*128 + g*16));
        *(uint4*)(smem + SM_B2H + soff) = *(const uint4*)(B2h_g + (size_t)(n0 + r)*64 + g*8);
        *(uint4*)(smem + SM_B2L + soff) = *(const uint4*)(B2l_g + (size_t)(n0 + r)*64 + g*8);
    }
    __syncthreads();

    const uint32_t aoff  = (uint32_t)((wm + (lane & 15))*128 + ((lane >> 4) << 4));
    const uint32_t boff0 = (uint32_t)((wn + (lane & 7) + ((lane >> 4) & 1)*8)*128 + ((lane >> 3) & 1)*16);
    const uint32_t boff1 = boff0 + 2048u;   // +16 B-rows
    const uint32_t ringb = SM_RING + (uint32_t)half*16384u;
    const int gs0 = half*4;

    for (int t = 0; t <= TT; t++) {
        const bool active = isZ ? (t < TT) : (t >= 1);
        float acc[4][4];
        if (active) {
            #pragma unroll
            for (int a = 0; a < 4; a++)
                #pragma unroll
                for (int c = 0; c < 4; c++) acc[a][c] = 0.f;

            // ---- u phase: both halves load, k16 split across halves ----
            int tu = isZ ? t : (t-1);
            const __nv_bfloat16* uh = Uh + (size_t)tu*BB*64;
            const __nv_bfloat16* ul = Ul + (size_t)tu*BB*64;
            {
                int r = tid >> 3, g = tid & 7;
                uint32_t off = SWZ((uint32_t)(r*128 + g*16));
                *(uint4*)(smem + SM_UST + off)         = *(const uint4*)(uh + (size_t)(m0 + r)*64 + g*8);
                *(uint4*)(smem + SM_UST + 4096u + off) = *(const uint4*)(ul + (size_t)(m0 + r)*64 + g*8);
            }
            __syncthreads();
            #pragma unroll
            for (int kk = 0; kk < 2; kk++) {
                int k16 = half*2 + kk;
                uint32_t ah[4], al[4], bh0[4], bh1[4], bl0[4], bl1[4];
                uint32_t ad = sb + SM_UST + SWZ(aoff + (uint32_t)k16*32);
                ldmx4(ah, ad); ldmx4(al, ad + 4096u);
                uint32_t bd0 = sb + SM_B2H + SWZ(boff0 + (uint32_t)k16*32);
                uint32_t bd1 = sb + SM_B2H + SWZ(boff1 + (uint32_t)k16*32);
                ldmx4(bh0, bd0); ldmx4(bh1, bd1);
                ldmx4(bl0, bd0 + 8192u); ldmx4(bl1, bd1 + 8192u);
                MMA_TRIPLE32(acc, ah, al, bh0, bh1, bl0, bl1)
            }
        }
        if (t > 0) gb_wait((unsigned)NCTA * (unsigned)t);

        if (active) {
            const __nv_bfloat16* zh = Zh + (size_t)(t & 1)*BB*DD;
            const __nv_bfloat16* zl = Zl + (size_t)(t & 1)*BB*DD;
            uint4 ph[2], pl[2];
            // prologue: slab gs0 -> slot1; prefetch gs0+1
            #pragma unroll
            for (int i = 0; i < 2; i++) {
                int idx = i*128 + htid;
                int r = idx >> 3, g = idx & 7;
                ph[i] = *(const uint4*)(zh + (size_t)(m0 + r)*DD + gs0*64 + g*8);
                pl[i] = *(const uint4*)(zl + (size_t)(m0 + r)*DD + gs0*64 + g*8);
            }
            {
                uint32_t zboff = ringb + 8192u;
                #pragma unroll
                for (int i = 0; i < 2; i++) {
                    int idx = i*128 + htid;
                    int r = idx >> 3, g = idx & 7;
                    uint32_t off = SWZ((uint32_t)(r*128 + g*16));
                    *(uint4*)(smem + zboff + off)         = ph[i];
                    *(uint4*)(smem + zboff + 4096u + off) = pl[i];
                }
            }
            #pragma unroll
            for (int i = 0; i < 2; i++) {
                int idx = i*128 + htid;
                int r = idx >> 3, g = idx & 7;
                ph[i] = *(const uint4*)(zh + (size_t)(m0 + r)*DD + (gs0+1)*64 + g*8);
                pl[i] = *(const uint4*)(zl + (size_t)(m0 + r)*DD + (gs0+1)*64 + g*8);
            }
            BARH(barid);

            // slab s computes from slot[(s+1)&1]; store slab s+1 -> slot[s&1]
            for (int s = 0; s < 4; s++) {
                int gs = gs0 + s;
                {
                    uint32_t zb = sb + ringb + (uint32_t)((s+1) & 1)*8192u;
                    uint32_t bb = sb + SM_BH + (uint32_t)gs*8192u;
                    #pragma unroll
                    for (int k16 = 0; k16 < 4; k16++) {
                        uint32_t ah[4], al[4], bh0[4], bh1[4], bl0[4], bl1[4];
                        uint32_t ad = zb + SWZ(aoff + (uint32_t)k16*32);
                        ldmx4(ah, ad); ldmx4(al, ad + 4096u);
                        uint32_t bd0 = bb + SWZ(boff0 + (uint32_t)k16*32);
                        uint32_t bd1 = bb + SWZ(boff1 + (uint32_t)k16*32);
                        ldmx4(bh0, bd0); ldmx4(bh1, bd1);
                        ldmx4(bl0, bd0 + 65536u); ldmx4(bl1, bd1 + 65536u);
                        MMA_TRIPLE32(acc, ah, al, bh0, bh1, bl0, bl1)
                    }
                }
                BARH(barid);
                if (s + 1 < 4) {
                    uint32_t zboff = ringb + (uint32_t)(s & 1)*8192u;
                    #pragma unroll
                    for (int i = 0; i < 2; i++) {
                        int idx = i*128 + htid;
                        int r = idx >> 3, g = idx & 7;
                        uint32_t off = SWZ((uint32_t)(r*128 + g*16));
                        *(uint4*)(smem + zboff + off)         = ph[i];
                        *(uint4*)(smem + zboff + 4096u + off) = pl[i];
                    }
                    if (s + 2 < 4) {
                        #pragma unroll
                        for (int i = 0; i < 2; i++) {
                            int idx = i*128 + htid;
                            int r = idx >> 3, g = idx & 7;
                            ph[i] = *(const uint4*)(zh + (size_t)(m0 + r)*DD + (gs+2)*64 + g*8);
                            pl[i] = *(const uint4*)(zl + (size_t)(m0 + r)*DD + (gs+2)*64 + g*8);
                        }
                    }
                    BARH(barid);
                }
            }

            // ---- cross-half reduction: half1 -> smem -> half0 adds ----
            __syncthreads();
            if (half == 1) {
                uint32_t ra = sb + SM_RED + (uint32_t)htid*64u;
                #pragma unroll
                for (int nj = 0; nj < 4; nj++)
                    asm volatile("st.shared.v4.b32 [%0], {%1,%2,%3,%4};"
                        :: "r"(ra + (uint32_t)nj*16u),
                           "r"(__float_as_uint(acc[nj][0])), "r"(__float_as_uint(acc[nj][1])),
                           "r"(__float_as_uint(acc[nj][2])), "r"(__float_as_uint(acc[nj][3])) : "memory");
            }
            __syncthreads();
            if (half == 0) {
                const float* red = (const float*)(smem + SM_RED) + htid*16;
                #pragma unroll
                for (int nj = 0; nj < 4; nj++)
                    #pragma unroll
                    for (int c = 0; c < 4; c++)
                        acc[nj][c] += red[nj*4 + c];

                int r0 = m0 + wm + (lane >> 2);
                int c0 = n0 + wn + (lane & 3)*2;
                if (isZ) {
                    float* Zout = Zo + (size_t)t*BB*DD;
                    __nv_bfloat16* zhn = Zh + (size_t)((t+1) & 1)*BB*DD;
                    __nv_bfloat16* zln = Zl + (size_t)((t+1) & 1)*BB*DD;
                    #pragma unroll
                    for (int nj = 0; nj < 4; nj++) {
                        int col = c0 + nj*8;
                        float a0 = acc[nj][0], a1 = acc[nj][1];
                        float a2 = acc[nj][2], a3 = acc[nj][3];
                        *(float2*)(Zout + (size_t)r0*DD + col)     = make_float2(a0, a1);
                        *(float2*)(Zout + (size_t)(r0+8)*DD + col) = make_float2(a2, a3);
                        __nv_bfloat162 h0 = __floats2bfloat162_rn(a0, a1);
                        __nv_bfloat162 l0 = __floats2bfloat162_rn(a0 - __bfloat162float(h0.x),
                                                                  a1 - __bfloat162float(h0.y));
                        __nv_bfloat162 h1 = __floats2bfloat162_rn(a2, a3);
                        __nv_bfloat162 l1 = __floats2bfloat162_rn(a2 - __bfloat162float(h1.x),
                                                                  a3 - __bfloat162float(h1.y));
                        *(__nv_bfloat162*)(zhn + (size_t)r0*DD + col)     = h0;
                        *(__nv_bfloat162*)(zln + (size_t)r0*DD + col)     = l0;
                        *(__nv_bfloat162*)(zhn + (size_t)(r0+8)*DD + col) = h1;
                        *(__nv_bfloat162*)(zln + (size_t)(r0+8)*DD + col) = l1;
                    }
                } else {
                    float* Yout = Yo + (size_t)(t-1)*BB*NOBS;
                    #pragma unroll
                    for (int nj = 0; nj < 4; nj++) {
                        int col = c0 + nj*8;
                        if (col < NOBS)     Yout[(size_t)r0*NOBS + col]       = acc[nj][0];
                        if (col + 1 < NOBS) Yout[(size_t)r0*NOBS + col + 1]   = acc[nj][1];
                        if (col < NOBS)     Yout[(size_t)(r0+8)*NOBS + col]   = acc[nj][2];
                        if (col + 1 < NOBS) Yout[(size_t)(r0+8)*NOBS + col+1] = acc[nj][3];
                    }
                }
            }
        }
        if (t < TT) gb_arrive(blk);
    }
}

// ---------------- host orchestration ----------------
extern "C" void kernel_launch(void* const* d_in, const int* in_sizes, int n_in,
                              void* d_out, int out_size)
{
    const float* z_dyn = (const float*)d_in[0];
    const float* dtp   = (const float*)d_in[2];
    const float* U     = (const float*)d_in[3];
    const float* skew  = (const float*)d_in[4];
    const float* gamma = (const float*)d_in[5];
    const float* B_ct  = (const float*)d_in[6];
    const float* Cm    = (const float*)d_in[7];
    const float* Dm    = (const float*)d_in[8];

    float *Y_, *Y2_, *Y3_, *T_, *T2_, *T3_, *E_, *P_, *Bb_;
    cudaGetSymbolAddress((void**)&Y_,  g_Y);
    cudaGetSymbolAddress((void**)&Y2_, g_Y2);
    cudaGetSymbolAddress((void**)&Y3_, g_Y3);
    cudaGetSymbolAddress((void**)&T_,  g_T);
    cudaGetSymbolAddress((void**)&T2_, g_T2);
    cudaGetSymbolAddress((void**)&T3_, g_T3);
    cudaGetSymbolAddress((void**)&E_,  g_E);
    cudaGetSymbolAddress((void**)&P_,  g_P);
    cudaGetSymbolAddress((void**)&Bb_, g_Bb);

    __nv_bfloat16 *Yht, *Ylt, *Eht, *Elt, *Pht, *Plt;
    __nv_bfloat16 *Ehi, *Elo, *Chi, *Clo, *Bbhi, *Bblo, *Dshi, *Dslo, *Zh, *Zl, *Uh, *Ul;
    cudaGetSymbolAddress((void**)&Yht,  g_Yht);
    cudaGetSymbolAddress((void**)&Ylt,  g_Ylt);
    cudaGetSymbolAddress((void**)&Eht,  g_Eht);
    cudaGetSymbolAddress((void**)&Elt,  g_Elt);
    cudaGetSymbolAddress((void**)&Pht,  g_Pht);
    cudaGetSymbolAddress((void**)&Plt,  g_Plt);
    cudaGetSymbolAddress((void**)&Ehi,  g_Ehi);
    cudaGetSymbolAddress((void**)&Elo,  g_Elo);
    cudaGetSymbolAddress((void**)&Chi,  g_Chi);
    cudaGetSymbolAddress((void**)&Clo,  g_Clo);
    cudaGetSymbolAddress((void**)&Bbhi, g_Bbhi);
    cudaGetSymbolAddress((void**)&Bblo, g_Bblo);
    cudaGetSymbolAddress((void**)&Dshi, g_Dshi);
    cudaGetSymbolAddress((void**)&Dslo, g_Dslo);
    cudaGetSymbolAddress((void**)&Zh,   g_Zh);
    cudaGetSymbolAddress((void**)&Zl,   g_Zl);
    cudaGetSymbolAddress((void**)&Uh,   g_Uh);
    cudaGetSymbolAddress((void**)&Ul,   g_Ul);

    cudaFuncSetAttribute(scan_persist, cudaFuncAttributeMaxDynamicSharedMemorySize, SM_TOT);
    cudaFuncSetAttribute(gemm_tc, cudaFuncAttributeMaxDynamicSharedMemorySize, TC_TOT);

    const int n2 = DD*DD;
    const int g2 = (n2 + 255)/256;
    dim3 gg1(16, 8, 1), gg2(16, 8, 2);
    const float4 z4  = make_float4(0.f, 0.f, 0.f, 0.f);
    const float4 D2E = make_float4(2.4801587e-05f, 2.7557319e-06f, 2.7557319e-07f, 2.5052108e-08f);
    const float4 D1E = make_float4(4.1666667e-02f, 8.3333333e-03f, 1.3888889e-03f, 1.9841270e-04f);
    const float4 D0E = make_float4(1.f, 1.f, 0.5f, 1.6666667e-01f);
    const float4 D2P = make_float4(2.7557319e-06f, 2.7557319e-07f, 2.5052108e-08f, 2.0876757e-09f);
    const float4 D1P = make_float4(8.3333333e-03f, 1.3888889e-03f, 1.9841270e-04f, 2.4801587e-05f);
    const float4 D0P = make_float4(1.f, 0.5f, 1.6666667e-01f, 4.1666667e-02f);

    build_Y_kernel<<<g2, 256>>>(skew, gamma, dtp, Y_);
    split_T<<<g2, 256>>>(Y_, Yht, Ylt);

    gemm_tc<<<gg1, 256, TC_TOT>>>(Y_, Y_, Yht, Ylt, Yht, Ylt, Y2_, Y2_,
                                  Eht, Elt, Eht, Elt, 1, 0,
                                  Y_, Y2_, Y3_, z4, z4, 0);
    gemm_tc<<<gg2, 256, TC_TOT>>>(Y2_, Y2_, Yht, Ylt, Eht, Elt, Y3_, T_,
                                  Pht, Plt, Pht, Plt, 0, 1,
                                  Y_, Y2_, Y3_, z4, z4, 0);
    init_H<<<g2, 256>>>(Y_, Y2_, Y3_, E_, P_);
    gemm_tc<<<gg2, 256, TC_TOT>>>(E_, P_, Pht, Plt, Pht, Plt, T2_, T3_,
                                  Pht, Plt, Pht, Plt, 0, 0,
                                  Y_, Y2_, Y3_, D2E, D2P, 1);
    gemm_tc<<<gg2, 256, TC_TOT>>>(T2_, T3_, Pht, Plt, Pht, Plt, E_, P_,
                                  Pht, Plt, Pht, Plt, 0, 0,
                                  Y_, Y2_, Y3_, D1E, D1P, 1);
    gemm_tc<<<gg2, 256, TC_TOT>>>(E_, P_, Pht, Plt, Pht, Plt, T2_, T3_,
                                  Pht, Plt, Pht, Plt, 0, 0,
                                  Y_, Y2_, Y3_, D0E, D0P, 1);
    gemm_small<<<16, 256>>>(Bb_, T3_, B_ct);

    split_mat<<<g2, 256>>>(T2_, Ehi, Elo, DD, DD, DD, DD, dtp, 0);
    split_mat<<<(64*DD + 255)/256, 256>>>(Cm, Chi, Clo, NOBS, DD, 64, DD, dtp, 0);
    split_mat<<<(DD*64 + 255)/256, 256>>>(Bb_, Bbhi, Bblo, DD, UDIM, DD, 64, dtp, 1);
    split_mat<<<(64*64 + 255)/256, 256>>>(Dm, Dshi, Dslo, NOBS, UDIM, 64, 64, dtp, 1);
    split_mat<<<g2, 256>>>(z_dyn, Zh, Zl, BB, DD, BB, DD, dtp, 0);
    split_mat<<<(TT*BB*64 + 255)/256, 256>>>(U, Uh, Ul, TT*BB, UDIM, TT*BB, 64, dtp, 0);

    reset_barrier<<<1, 32>>>();

    float* Zo = (float*)d_out;
    float* Yo = (float*)d_out + (size_t)TT*BB*DD;
    scan_persist<<<NCTA, 256, SM_TOT>>>(Zo, Yo,
                                        Ehi, Elo, Bbhi, Bblo, Chi, Clo, Dshi, Dslo,
                                        Zh, Zl, Uh, Ul);
}

// round 17
// speedup vs baseline: 1.3491x; 1.0427x over previous
#include <cuda_runtime.h>
#include <cuda_bf16.h>
#include <math.h>
#include <stdint.h>

#define DD   512
#define BB   512
#define TT   256
#define UDIM 32
#define NOBS 50
#define NCTA 144

// ---------------- device scratch ----------------
__device__ float g_Y [DD*DD];
__device__ float g_Y2[DD*DD];
__device__ float g_Y3[DD*DD];
__device__ float g_T [DD*DD];
__device__ float g_T2[DD*DD];
__device__ float g_T3[DD*DD];
__device__ float g_E [DD*DD];
__device__ float g_P [DD*DD];
__device__ float g_Bb[DD*UDIM];

__device__ __nv_bfloat16 g_Yht [DD*DD];
__device__ __nv_bfloat16 g_Ylt [DD*DD];
__device__ __nv_bfloat16 g_Eht [DD*DD];   // Y2 split
__device__ __nv_bfloat16 g_Elt [DD*DD];
__device__ __nv_bfloat16 g_Pht [DD*DD];   // Y4 split
__device__ __nv_bfloat16 g_Plt [DD*DD];

__device__ __nv_bfloat16 g_Ehi [DD*DD];
__device__ __nv_bfloat16 g_Elo [DD*DD];
__device__ __nv_bfloat16 g_Chi [64*DD];
__device__ __nv_bfloat16 g_Clo [64*DD];
__device__ __nv_bfloat16 g_Bbhi[DD*64];
__device__ __nv_bfloat16 g_Bblo[DD*64];
__device__ __nv_bfloat16 g_Dshi[64*64];
__device__ __nv_bfloat16 g_Dslo[64*64];

__device__ __nv_bfloat16 g_Zh[2*BB*DD];
__device__ __nv_bfloat16 g_Zl[2*BB*DD];
__device__ __nv_bfloat16 g_Uh[(size_t)TT*BB*64];
__device__ __nv_bfloat16 g_Ul[(size_t)TT*BB*64];

__device__ __align__(128) unsigned g_cnt[8*32];

// ---------------- helpers ----------------
__device__ __forceinline__ uint32_t smem_u32(const void* p) {
    uint32_t a;
    asm("{ .reg .u64 t; cvta.to.shared.u64 t, %1; cvt.u32.u64 %0, t; }" : "=r"(a) : "l"(p));
    return a;
}
#define SWZ(o) ((o) ^ (((o) >> 3) & 0x70))
#define BARH(id) asm volatile("bar.sync %0, 128;" :: "r"(id) : "memory")

__device__ __forceinline__ void ldmx4(uint32_t r[4], uint32_t addr) {
    asm volatile("ldmatrix.sync.aligned.m8n8.x4.shared.b16 {%0,%1,%2,%3}, [%4];"
        : "=r"(r[0]), "=r"(r[1]), "=r"(r[2]), "=r"(r[3]) : "r"(addr));
}
__device__ __forceinline__ void mma16816(float acc[4], const uint32_t a[4],
                                          uint32_t b0, uint32_t b1) {
    asm volatile("mma.sync.aligned.m16n8k16.row.col.f32.bf16.bf16.f32 "
        "{%0,%1,%2,%3},{%4,%5,%6,%7},{%8,%9},{%0,%1,%2,%3};"
        : "+f"(acc[0]), "+f"(acc[1]), "+f"(acc[2]), "+f"(acc[3])
        : "r"(a[0]), "r"(a[1]), "r"(a[2]), "r"(a[3]), "r"(b0), "r"(b1));
}
__device__ __forceinline__ void split4(float4 v, uint32_t hi_a, uint32_t lo_a) {
    __nv_bfloat162 h0 = __floats2bfloat162_rn(v.x, v.y);
    __nv_bfloat162 h1 = __floats2bfloat162_rn(v.z, v.w);
    __nv_bfloat162 l0 = __floats2bfloat162_rn(v.x - __bfloat162float(h0.x), v.y - __bfloat162float(h0.y));
    __nv_bfloat162 l1 = __floats2bfloat162_rn(v.z - __bfloat162float(h1.x), v.w - __bfloat162float(h1.y));
    uint32_t h0u = *(uint32_t*)&h0, h1u = *(uint32_t*)&h1;
    uint32_t l0u = *(uint32_t*)&l0, l1u = *(uint32_t*)&l1;
    asm volatile("st.shared.v2.b32 [%0], {%1,%2};" :: "r"(hi_a), "r"(h0u), "r"(h1u) : "memory");
    asm volatile("st.shared.v2.b32 [%0], {%1,%2};" :: "r"(lo_a), "r"(l0u), "r"(l1u) : "memory");
}
#define MMA_TRIPLE(accw, ahh, all, bhh, bll) \
    mma16816(accw[0][0], ahh##0, bhh[0], bhh[1]); \
    mma16816(accw[0][1], ahh##0, bhh[2], bhh[3]); \
    mma16816(accw[1][0], ahh##1, bhh[0], bhh[1]); \
    mma16816(accw[1][1], ahh##1, bhh[2], bhh[3]); \
    mma16816(accw[0][0], all##0, bhh[0], bhh[1]); \
    mma16816(accw[0][1], all##0, bhh[2], bhh[3]); \
    mma16816(accw[1][0], all##1, bhh[0], bhh[1]); \
    mma16816(accw[1][1], all##1, bhh[2], bhh[3]); \
    mma16816(accw[0][0], ahh##0, bll[0], bll[1]); \
    mma16816(accw[0][1], ahh##0, bll[2], bll[3]); \
    mma16816(accw[1][0], ahh##1, bll[0], bll[1]); \
    mma16816(accw[1][1], ahh##1, bll[2], bll[3]);

// 12-MMA triple for M16xN32 warp tile
#define MMA_TRIPLE32(accw, ah, al, bh0, bh1, bl0, bl1) \
    mma16816(accw[0], ah, bh0[0], bh0[1]); \
    mma16816(accw[1], ah, bh0[2], bh0[3]); \
    mma16816(accw[2], ah, bh1[0], bh1[1]); \
    mma16816(accw[3], ah, bh1[2], bh1[3]); \
    mma16816(accw[0], al, bh0[0], bh0[1]); \
    mma16816(accw[1], al, bh0[2], bh0[3]); \
    mma16816(accw[2], al, bh1[0], bh1[1]); \
    mma16816(accw[3], al, bh1[2], bh1[3]); \
    mma16816(accw[0], ah, bl0[0], bl0[1]); \
    mma16816(accw[1], ah, bl0[2], bl0[3]); \
    mma16816(accw[2], ah, bl1[0], bl1[1]); \
    mma16816(accw[3], ah, bl1[2], bl1[3]);

// ---------------- setup elementwise kernels (R15 verbatim) ----------------
__global__ void build_Y_kernel(const float* __restrict__ skew, const float* __restrict__ gamma,
                               const float* __restrict__ dtp, float* __restrict__ Y)
{
    int idx = blockIdx.x*256 + threadIdx.x;
    if (idx >= DD*DD) return;
    int i = idx >> 9, j = idx & (DD-1);
    float v;
    if (i < j)      v =  skew[i*(DD-1) - (i*(i-1))/2 + (j-i-1)];
    else if (i > j) v = -skew[j*(DD-1) - (j*(j-1))/2 + (i-j-1)];
    else { float g = gamma[i]; v = -(fmaxf(g,0.f) + log1pf(expf(-fabsf(g)))); }
    Y[idx] = v * dtp[0];
}
__global__ void reset_barrier() { if (threadIdx.x < 8) g_cnt[threadIdx.x*32] = 0; }

__global__ void split_T(const float* __restrict__ src,
                        __nv_bfloat16* __restrict__ h, __nv_bfloat16* __restrict__ l)
{
    int idx = blockIdx.x*256 + threadIdx.x;
    if (idx >= DD*DD) return;
    int r = idx >> 9, c = idx & (DD-1);
    float v = src[idx];
    __nv_bfloat16 hh = __float2bfloat16(v);
    h[(size_t)c*DD + r] = hh;
    l[(size_t)c*DD + r] = __float2bfloat16(v - __bfloat162float(hh));
}
__global__ void split_mat(const float* __restrict__ src, __nv_bfloat16* hi, __nv_bfloat16* lo,
                          int rs, int cs, int rd, int cd, const float* dtp, int usedt)
{
    int idx = blockIdx.x*256 + threadIdx.x;
    if (idx >= rd*cd) return;
    int r = idx / cd, c = idx % cd;
    float v = (r < rs && c < cs) ? src[(size_t)r*cs + c] : 0.f;
    if (usedt) v *= dtp[0];
    __nv_bfloat16 h = __float2bfloat16(v);
    hi[idx] = h;
    lo[idx] = __float2bfloat16(v - __bfloat162float(h));
}
__global__ void init_H(const float* __restrict__ Y, const float* __restrict__ Y2,
                       const float* __restrict__ Y3, float* __restrict__ HE, float* __restrict__ HP)
{
    int idx = blockIdx.x*256 + threadIdx.x;
    if (idx >= DD*DD) return;
    float dg = ((idx>>9) == (idx&(DD-1))) ? 1.f : 0.f;
    float y = Y[idx], y2 = Y2[idx], y3 = Y3[idx];
    HE[idx] = 2.0876757e-09f*dg + 1.6059044e-10f*y + 1.1470746e-11f*y2 + 7.6471637e-13f*y3;
    HP[idx] = 1.6059044e-10f*dg + 1.1470746e-11f*y + 7.6471637e-13f*y2 + 4.7794773e-14f*y3;
}
__global__ void gemm_small(float* __restrict__ C, const float* __restrict__ A,
                           const float* __restrict__ Bm)
{
    __shared__ float As[32][33];
    __shared__ float Bs[32][33];
    int tx = threadIdx.x & 15, ty = threadIdx.x >> 4;
    int i0 = blockIdx.x*32;
    float a00=0,a01=0,a10=0,a11=0;
    for (int k0 = 0; k0 < DD; k0 += 32) {
        for (int u = threadIdx.x; u < 32*32; u += 256) {
            int r = u>>5, c = u&31;
            As[r][c] = A[(size_t)(i0+r)*DD + k0+c];
            Bs[r][c] = Bm[(size_t)(k0+r)*UDIM + c];
        }
        __syncthreads();
        #pragma unroll
        for (int k = 0; k < 32; k++) {
            float x0=As[ty*2][k], x1=As[ty*2+1][k];
            float y0=Bs[k][tx*2], y1=Bs[k][tx*2+1];
            a00+=x0*y0; a01+=x0*y1; a10+=x1*y0; a11+=x1*y1;
        }
        __syncthreads();
    }
    C[(size_t)(i0+ty*2+0)*UDIM + tx*2+0]=a00;
    C[(size_t)(i0+ty*2+0)*UDIM + tx*2+1]=a01;
    C[(size_t)(i0+ty*2+1)*UDIM + tx*2+0]=a10;
    C[(size_t)(i0+ty*2+1)*UDIM + tx*2+1]=a11;
}

// ---------------- tensor-core setup GEMM (R15 verbatim) ----------------
#define TC_BH  0u
#define TC_BL  32768u
#define TC_ZR  65536u
#define TC_TOT 131072u

__global__ void __launch_bounds__(256) gemm_tc(
    const float* __restrict__ A0, const float* __restrict__ A1,
    const __nv_bfloat16* __restrict__ Bh0, const __nv_bfloat16* __restrict__ Bl0,
    const __nv_bfloat16* __restrict__ Bh1, const __nv_bfloat16* __restrict__ Bl1,
    float* __restrict__ C0, float* __restrict__ C1,
    __nv_bfloat16* __restrict__ Th0, __nv_bfloat16* __restrict__ Tl0,
    __nv_bfloat16* __restrict__ Th1, __nv_bfloat16* __restrict__ Tl1,
    int split0, int split1,
    const float* __restrict__ Yp, const float* __restrict__ Y2p, const float* __restrict__ Y3p,
    float4 cadd0, float4 cadd1, int addmode)
{
    extern __shared__ __align__(1024) char smem[];
    const int tid = threadIdx.x, lane = tid & 31, w = tid >> 5;
    const int half = w >> 2, wsub = w & 3;
    const int wm = (wsub & 1)*32, wn = (wsub >> 1)*16;
    const int htid = tid & 127;
    const int barid = 1 + half;
    const int n0 = blockIdx.x*32, m0 = blockIdx.y*64;
    const int z = blockIdx.z;
    const float* A = z ? A1 : A0;
    const __nv_bfloat16* Bh = z ? Bh1 : Bh0;
    const __nv_bfloat16* Bl = z ? Bl1 : Bl0;
    const uint32_t sb = smem_u32(smem);

    #pragma unroll
    for (int i = 0; i < 8; i++) {
        int idx = i*256 + tid;
        int r = idx >> 6, g = idx & 63;
        uint32_t soff = (uint32_t)((g>>3)*4096) + SWZ((uint32_t)(r*128 + (g&7)*16));
        *(uint4*)(smem + TC_BH + soff) = *(const uint4*)(Bh + (size_t)(n0+r)*DD + g*8);
        *(uint4*)(smem + TC_BL + soff) = *(const uint4*)(Bl + (size_t)(n0+r)*DD + g*8);
    }
    __syncthreads();

    const uint32_t aoff0 = (uint32_t)((wm + 0  + (lane & 15))*128 + ((lane >> 4) << 4));
    const uint32_t aoff1 = (uint32_t)((wm + 16 + (lane & 15))*128 + ((lane >> 4) << 4));
    const uint32_t boff  = (uint32_t)((wn + (lane & 7) + ((lane >> 4) & 1)*8)*128 + ((lane >> 3) & 1)*16);
    const int ldr = htid >> 4, lfq = htid & 15;
    const uint32_t ringb = TC_ZR + (uint32_t)half*32768u;
    const int gs0 = half*4;

    float acc[2][2][4];
    #pragma unroll
    for (int a = 0; a < 2; a++)
        #pragma unroll
        for (int b = 0; b < 2; b++)
            #pragma unroll
            for (int c = 0; c < 4; c++) acc[a][b][c] = 0.f;

    float4 pf[8];
    #pragma unroll
    for (int i = 0; i < 8; i++)
        pf[i] = *(const float4*)(A + (size_t)(m0 + i*8 + ldr)*DD + gs0*64 + lfq*4);
    {
        uint32_t zb = sb + ringb + 16384u;
        #pragma unroll
        for (int i = 0; i < 8; i++) {
            uint32_t off = SWZ((uint32_t)((i*8+ldr)*128 + lfq*8));
            split4(pf[i], zb + off, zb + 8192u + off);
        }
    }
    BARH(barid);

    for (int s = 0; s < 4; s++) {
        int gs = gs0 + s;
        if (s + 1 < 4) {
            #pragma unroll
            for (int i = 0; i < 8; i++)
                pf[i] = *(const float4*)(A + (size_t)(m0 + i*8 + ldr)*DD + (gs+1)*64 + lfq*4);
        }
        {
            uint32_t zb = sb + ringb + (uint32_t)((s+1) & 1)*16384u;
            uint32_t bb = sb + TC_BH + (uint32_t)gs*4096u;
            #pragma unroll
            for (int k16 = 0; k16 < 4; k16++) {
                uint32_t ah0[4], al0[4], ah1[4], al1[4], bh[4], bl[4];
                uint32_t ad0 = zb + SWZ(aoff0 + (uint32_t)k16*32);
                ldmx4(ah0, ad0); ldmx4(al0, ad0 + 8192u);
                uint32_t ad1 = zb + SWZ(aoff1 + (uint32_t)k16*32);
                ldmx4(ah1, ad1); ldmx4(al1, ad1 + 8192u);
                uint32_t bd = bb + SWZ(boff + (uint32_t)k16*32);
                ldmx4(bh, bd); ldmx4(bl, bd + 32768u);
                MMA_TRIPLE(acc, ah, al, bh, bl)
            }
        }
        BARH(barid);
        if (s + 1 < 4) {
            uint32_t zb = sb + ringb + (uint32_t)(s & 1)*16384u;
            #pragma unroll
            for (int i = 0; i < 8; i++) {
                uint32_t off = SWZ((uint32_t)((i*8+ldr)*128 + lfq*8));
                split4(pf[i], zb + off, zb + 8192u + off);
            }
            BARH(barid);
        }
    }

    __syncthreads();
    if (half == 1) {
        uint32_t ra = sb + TC_ZR + 32768u + (uint32_t)htid*64u;
        #pragma unroll
        for (int mi = 0; mi < 2; mi++)
            #pragma unroll
            for (int ni = 0; ni < 2; ni++)
                asm volatile("st.shared.v4.b32 [%0], {%1,%2,%3,%4};"
                    :: "r"(ra + (uint32_t)(mi*2+ni)*16u),
                       "r"(__float_as_uint(acc[mi][ni][0])), "r"(__float_as_uint(acc[mi][ni][1])),
                       "r"(__float_as_uint(acc[mi][ni][2])), "r"(__float_as_uint(acc[mi][ni][3])) : "memory");
    }
    __syncthreads();
    if (half != 0) return;
    {
        const float* red = (const float*)(smem + TC_ZR + 32768u) + htid*16;
        #pragma unroll
        for (int mi = 0; mi < 2; mi++)
            #pragma unroll
            for (int ni = 0; ni < 2; ni++)
                #pragma unroll
                for (int c = 0; c < 4; c++)
                    acc[mi][ni][c] += red[(mi*2+ni)*4 + c];
    }

    int r0 = m0 + wm + (lane >> 2);
    int c0 = n0 + wn + (lane & 3)*2;
    float* Cw = z ? C1 : C0;
    __nv_bfloat16* Th = z ? Th1 : Th0;
    __nv_bfloat16* Tl = z ? Tl1 : Tl0;
    const int dosplit = z ? split1 : split0;
    const float4 ca = z ? cadd1 : cadd0;

    #pragma unroll
    for (int mi = 0; mi < 2; mi++)
        #pragma unroll
        for (int ni = 0; ni < 2; ni++)
            #pragma unroll
            for (int h = 0; h < 2; h++) {
                int rr = r0 + mi*16 + h*8, cc = c0 + ni*8;
                size_t idx = (size_t)rr*DD + cc;
                float v0 = acc[mi][ni][h*2+0];
                float v1 = acc[mi][ni][h*2+1];
                if (addmode) {
                    float2 y  = *(const float2*)(Yp  + idx);
                    float2 y2 = *(const float2*)(Y2p + idx);
                    float2 y3 = *(const float2*)(Y3p + idx);
                    v0 += ca.y*y.x + ca.z*y2.x + ca.w*y3.x + ((rr == cc)   ? ca.x : 0.f);
                    v1 += ca.y*y.y + ca.z*y2.y + ca.w*y3.y + ((rr == cc+1) ? ca.x : 0.f);
                }
                *(float2*)(Cw + idx) = make_float2(v0, v1);
                if (dosplit) {
                    __nv_bfloat16 h0 = __float2bfloat16(v0);
                    __nv_bfloat16 h1 = __float2bfloat16(v1);
                    Th[(size_t)cc*DD + rr]     = h0;
                    Tl[(size_t)cc*DD + rr]     = __float2bfloat16(v0 - __bfloat162float(h0));
                    Th[(size_t)(cc+1)*DD + rr] = h1;
                    Tl[(size_t)(cc+1)*DD + rr] = __float2bfloat16(v1 - __bfloat162float(h1));
                }
            }
}

// ---------------- persistent mma scan: M32 x N64, 3-slot ring, 1 BARH/slab ----------------
// smem: Bop hi 64K | Bop lo 64K | B2 hi 8K | B2 lo 8K | ustage 8K | ring 2x3x8K | red 8K
#define SM_BH   0u
#define SM_BL   65536u
#define SM_B2H  131072u
#define SM_B2L  139264u
#define SM_UST  147456u
#define SM_RING 155648u
#define SM_RED  204800u
#define SM_TOT  212992u

__device__ __forceinline__ void gb_arrive(int blk) {
    __syncthreads();
    if (threadIdx.x == 0) {
        __threadfence();
        atomicAdd(&g_cnt[(blk & 7)*32], 1u);
    }
}
__device__ __forceinline__ void gb_wait(unsigned want) {
    if (threadIdx.x == 0) {
        unsigned s;
        do {
            s = 0;
            #pragma unroll
            for (int i = 0; i < 8; i++) s += *(volatile unsigned*)&g_cnt[i*32];
        } while (s < want);
        __threadfence();
    }
    __syncthreads();
}

__global__ void __launch_bounds__(256) scan_persist(
    float* __restrict__ Zo, float* __restrict__ Yo,
    const __nv_bfloat16* __restrict__ Ehi,  const __nv_bfloat16* __restrict__ Elo,
    const __nv_bfloat16* __restrict__ Bbhi, const __nv_bfloat16* __restrict__ Bblo,
    const __nv_bfloat16* __restrict__ Chi,  const __nv_bfloat16* __restrict__ Clo,
    const __nv_bfloat16* __restrict__ Dshi, const __nv_bfloat16* __restrict__ Dslo,
    __nv_bfloat16* __restrict__ Zh, __nv_bfloat16* __restrict__ Zl,
    const __nv_bfloat16* __restrict__ Uh, const __nv_bfloat16* __restrict__ Ul)
{
    extern __shared__ __align__(1024) char smem[];
    const int tid  = threadIdx.x;
    const int lane = tid & 31;
    const int w    = tid >> 5;
    const int half = w >> 2;
    const int wsub = w & 3;
    const int wm = (wsub & 1) * 16;
    const int wn = (wsub >> 1) * 32;
    const int htid = tid & 127;
    const int barid = 1 + half;
    const int blk = blockIdx.x;
    const bool isZ = blk < 128;

    int m0, n0;
    const __nv_bfloat16 *Bh_g, *Bl_g, *B2h_g, *B2l_g;
    if (isZ) {
        m0 = (blk >> 3) * 32; n0 = (blk & 7) * 64;
        Bh_g = Ehi; Bl_g = Elo; B2h_g = Bbhi; B2l_g = Bblo;
    } else {
        int local = blk - 128;
        m0 = local * 32; n0 = 0;
        Bh_g = Chi; Bl_g = Clo; B2h_g = Dshi; B2l_g = Dslo;
    }

    const uint32_t sb = smem_u32(smem);

    #pragma unroll
    for (int i = 0; i < 16; i++) {
        int idx = i*256 + tid;
        int r = idx >> 6, g = idx & 63;
        uint32_t soff = (uint32_t)((g >> 3)*8192) + SWZ((uint32_t)(r*128 + (g & 7)*16));
        *(uint4*)(smem + SM_BH + soff) = *(const uint4*)(Bh_g + (size_t)(n0 + r)*DD + g*8);
        *(uint4*)(smem + SM_BL + soff) = *(const uint4*)(Bl_g + (size_t)(n0 + r)*DD + g*8);
    }
    #pragma unroll
    for (int i = 0; i < 2; i++) {
        int idx = i*256 + tid;
        int r = idx >> 3, g = idx & 7;
        uint32_t soff = SWZ((uint32_t)(r*128 + g*16));
        *(uint4*)(smem + SM_B2H + soff) = *(const uint4*)(B2h_g + (size_t)(n0 + r)*64 + g*8);
        *(uint4*)(smem + SM_B2L + soff) = *(const uint4*)(B2l_g + (size_t)(n0 + r)*64 + g*8);
    }
    __syncthreads();

    const uint32_t aoff  = (uint32_t)((wm + (lane & 15))*128 + ((lane >> 4) << 4));
    const uint32_t boff0 = (uint32_t)((wn + (lane & 7) + ((lane >> 4) & 1)*8)*128 + ((lane >> 3) & 1)*16);
    const uint32_t boff1 = boff0 + 2048u;
    const uint32_t ringb = SM_RING + (uint32_t)half*24576u;   // 3 slots x 8KB per half
    const int gs0 = half*4;

    for (int t = 0; t <= TT; t++) {
        const bool active = isZ ? (t < TT) : (t >= 1);
        float acc[4][4];
        if (active) {
            #pragma unroll
            for (int a = 0; a < 4; a++)
                #pragma unroll
                for (int c = 0; c < 4; c++) acc[a][c] = 0.f;

            // ---- u phase (pre-barrier) ----
            int tu = isZ ? t : (t-1);
            const __nv_bfloat16* uh = Uh + (size_t)tu*BB*64;
            const __nv_bfloat16* ul = Ul + (size_t)tu*BB*64;
            {
                int r = tid >> 3, g = tid & 7;
                uint32_t off = SWZ((uint32_t)(r*128 + g*16));
                *(uint4*)(smem + SM_UST + off)         = *(const uint4*)(uh + (size_t)(m0 + r)*64 + g*8);
                *(uint4*)(smem + SM_UST + 4096u + off) = *(const uint4*)(ul + (size_t)(m0 + r)*64 + g*8);
            }
            __syncthreads();
            #pragma unroll
            for (int kk = 0; kk < 2; kk++) {
                int k16 = half*2 + kk;
                uint32_t ah[4], al[4], bh0[4], bh1[4], bl0[4], bl1[4];
                uint32_t ad = sb + SM_UST + SWZ(aoff + (uint32_t)k16*32);
                ldmx4(ah, ad); ldmx4(al, ad + 4096u);
                uint32_t bd0 = sb + SM_B2H + SWZ(boff0 + (uint32_t)k16*32);
                uint32_t bd1 = sb + SM_B2H + SWZ(boff1 + (uint32_t)k16*32);
                ldmx4(bh0, bd0); ldmx4(bh1, bd1);
                ldmx4(bl0, bd0 + 8192u); ldmx4(bl1, bd1 + 8192u);
                MMA_TRIPLE32(acc, ah, al, bh0, bh1, bl0, bl1)
            }
        }
        if (t > 0) gb_wait((unsigned)NCTA * (unsigned)t);

        if (active) {
            const __nv_bfloat16* zh = Zh + (size_t)(t & 1)*BB*DD;
            const __nv_bfloat16* zl = Zl + (size_t)(t & 1)*BB*DD;
            uint4 ph[2], pl[2];
            // prologue: load slab gs0, store -> slot0; prefetch slab gs0+1; BARH
            #pragma unroll
            for (int i = 0; i < 2; i++) {
                int idx = i*128 + htid;
                int r = idx >> 3, g = idx & 7;
                ph[i] = *(const uint4*)(zh + (size_t)(m0 + r)*DD + gs0*64 + g*8);
                pl[i] = *(const uint4*)(zl + (size_t)(m0 + r)*DD + gs0*64 + g*8);
            }
            #pragma unroll
            for (int i = 0; i < 2; i++) {
                int idx = i*128 + htid;
                int r = idx >> 3, g = idx & 7;
                uint32_t off = SWZ((uint32_t)(r*128 + g*16));
                *(uint4*)(smem + ringb + off)         = ph[i];
                *(uint4*)(smem + ringb + 4096u + off) = pl[i];
            }
            #pragma unroll
            for (int i = 0; i < 2; i++) {
                int idx = i*128 + htid;
                int r = idx >> 3, g = idx & 7;
                ph[i] = *(const uint4*)(zh + (size_t)(m0 + r)*DD + (gs0+1)*64 + g*8);
                pl[i] = *(const uint4*)(zl + (size_t)(m0 + r)*DD + (gs0+1)*64 + g*8);
            }
            BARH(barid);

            // slab s: compute from slot[s%3]; store slab s+1 -> slot[(s+1)%3]; 1 BARH
            #pragma unroll
            for (int s = 0; s < 4; s++) {
                int gs = gs0 + s;
                if (s + 1 < 4) {
                    uint32_t zboff = ringb + (uint32_t)(((s+1) % 3))*8192u;
                    #pragma unroll
                    for (int i = 0; i < 2; i++) {
                        int idx = i*128 + htid;
                        int r = idx >> 3, g = idx & 7;
                        uint32_t off = SWZ((uint32_t)(r*128 + g*16));
                        *(uint4*)(smem + zboff + off)         = ph[i];
                        *(uint4*)(smem + zboff + 4096u + off) = pl[i];
                    }
                    if (s + 2 < 4) {
                        #pragma unroll
                        for (int i = 0; i < 2; i++) {
                            int idx = i*128 + htid;
                            int r = idx >> 3, g = idx & 7;
                            ph[i] = *(const uint4*)(zh + (size_t)(m0 + r)*DD + (gs+2)*64 + g*8);
                            pl[i] = *(const uint4*)(zl + (size_t)(m0 + r)*DD + (gs+2)*64 + g*8);
                        }
                    }
                }
                {
                    uint32_t zb = sb + ringb + (uint32_t)(s % 3)*8192u;
                    uint32_t bb = sb + SM_BH + (uint32_t)gs*8192u;
                    #pragma unroll
                    for (int k16 = 0; k16 < 4; k16++) {
                        uint32_t ah[4], al[4], bh0[4], bh1[4], bl0[4], bl1[4];
                        uint32_t ad = zb + SWZ(aoff + (uint32_t)k16*32);
                        ldmx4(ah, ad); ldmx4(al, ad + 4096u);
                        uint32_t bd0 = bb + SWZ(boff0 + (uint32_t)k16*32);
                        uint32_t bd1 = bb + SWZ(boff1 + (uint32_t)k16*32);
                        ldmx4(bh0, bd0); ldmx4(bh1, bd1);
                        ldmx4(bl0, bd0 + 65536u); ldmx4(bl1, bd1 + 65536u);
                        MMA_TRIPLE32(acc, ah, al, bh0, bh1, bl0, bl1)
                    }
                }
                BARH(barid);
            }

            // ---- cross-half reduction: half1 -> smem -> half0 adds ----
            if (half == 1) {
                uint32_t ra = sb + SM_RED + (uint32_t)htid*64u;
                #pragma unroll
                for (int nj = 0; nj < 4; nj++)
                    asm volatile("st.shared.v4.b32 [%0], {%1,%2,%3,%4};"
                        :: "r"(ra + (uint32_t)nj*16u),
                           "r"(__float_as_uint(acc[nj][0])), "r"(__float_as_uint(acc[nj][1])),
                           "r"(__float_as_uint(acc[nj][2])), "r"(__float_as_uint(acc[nj][3])) : "memory");
            }
            __syncthreads();
            if (half == 0) {
                const float* red = (const float*)(smem + SM_RED) + htid*16;
                #pragma unroll
                for (int nj = 0; nj < 4; nj++)
                    #pragma unroll
                    for (int c = 0; c < 4; c++)
                        acc[nj][c] += red[nj*4 + c];

                int r0 = m0 + wm + (lane >> 2);
                int c0 = n0 + wn + (lane & 3)*2;
                if (isZ) {
                    float* Zout = Zo + (size_t)t*BB*DD;
                    __nv_bfloat16* zhn = Zh + (size_t)((t+1) & 1)*BB*DD;
                    __nv_bfloat16* zln = Zl + (size_t)((t+1) & 1)*BB*DD;
                    #pragma unroll
                    for (int nj = 0; nj < 4; nj++) {
                        int col = c0 + nj*8;
                        float a0 = acc[nj][0], a1 = acc[nj][1];
                        float a2 = acc[nj][2], a3 = acc[nj][3];
                        *(float2*)(Zout + (size_t)r0*DD + col)     = make_float2(a0, a1);
                        *(float2*)(Zout + (size_t)(r0+8)*DD + col) = make_float2(a2, a3);
                        __nv_bfloat162 h0 = __floats2bfloat162_rn(a0, a1);
                        __nv_bfloat162 l0 = __floats2bfloat162_rn(a0 - __bfloat162float(h0.x),
                                                                  a1 - __bfloat162float(h0.y));
                        __nv_bfloat162 h1 = __floats2bfloat162_rn(a2, a3);
                        __nv_bfloat162 l1 = __floats2bfloat162_rn(a2 - __bfloat162float(h1.x),
                                                                  a3 - __bfloat162float(h1.y));
                        *(__nv_bfloat162*)(zhn + (size_t)r0*DD + col)     = h0;
                        *(__nv_bfloat162*)(zln + (size_t)r0*DD + col)     = l0;
                        *(__nv_bfloat162*)(zhn + (size_t)(r0+8)*DD + col) = h1;
                        *(__nv_bfloat162*)(zln + (size_t)(r0+8)*DD + col) = l1;
                    }
                } else {
                    float* Yout = Yo + (size_t)(t-1)*BB*NOBS;
                    #pragma unroll
                    for (int nj = 0; nj < 4; nj++) {
                        int col = c0 + nj*8;
                        if (col < NOBS)     Yout[(size_t)r0*NOBS + col]       = acc[nj][0];
                        if (col + 1 < NOBS) Yout[(size_t)r0*NOBS + col + 1]   = acc[nj][1];
                        if (col < NOBS)     Yout[(size_t)(r0+8)*NOBS + col]   = acc[nj][2];
                        if (col + 1 < NOBS) Yout[(size_t)(r0+8)*NOBS + col+1] = acc[nj][3];
                    }
                }
            }
        }
        if (t < TT) gb_arrive(blk);
    }
}

// ---------------- host orchestration ----------------
extern "C" void kernel_launch(void* const* d_in, const int* in_sizes, int n_in,
                              void* d_out, int out_size)
{
    const float* z_dyn = (const float*)d_in[0];
    const float* dtp   = (const float*)d_in[2];
    const float* U     = (const float*)d_in[3];
    const float* skew  = (const float*)d_in[4];
    const float* gamma = (const float*)d_in[5];
    const float* B_ct  = (const float*)d_in[6];
    const float* Cm    = (const float*)d_in[7];
    const float* Dm    = (const float*)d_in[8];

    float *Y_, *Y2_, *Y3_, *T_, *T2_, *T3_, *E_, *P_, *Bb_;
    cudaGetSymbolAddress((void**)&Y_,  g_Y);
    cudaGetSymbolAddress((void**)&Y2_, g_Y2);
    cudaGetSymbolAddress((void**)&Y3_, g_Y3);
    cudaGetSymbolAddress((void**)&T_,  g_T);
    cudaGetSymbolAddress((void**)&T2_, g_T2);
    cudaGetSymbolAddress((void**)&T3_, g_T3);
    cudaGetSymbolAddress((void**)&E_,  g_E);
    cudaGetSymbolAddress((void**)&P_,  g_P);
    cudaGetSymbolAddress((void**)&Bb_, g_Bb);

    __nv_bfloat16 *Yht, *Ylt, *Eht, *Elt, *Pht, *Plt;
    __nv_bfloat16 *Ehi, *Elo, *Chi, *Clo, *Bbhi, *Bblo, *Dshi, *Dslo, *Zh, *Zl, *Uh, *Ul;
    cudaGetSymbolAddress((void**)&Yht,  g_Yht);
    cudaGetSymbolAddress((void**)&Ylt,  g_Ylt);
    cudaGetSymbolAddress((void**)&Eht,  g_Eht);
    cudaGetSymbolAddress((void**)&Elt,  g_Elt);
    cudaGetSymbolAddress((void**)&Pht,  g_Pht);
    cudaGetSymbolAddress((void**)&Plt,  g_Plt);
    cudaGetSymbolAddress((void**)&Ehi,  g_Ehi);
    cudaGetSymbolAddress((void**)&Elo,  g_Elo);
    cudaGetSymbolAddress((void**)&Chi,  g_Chi);
    cudaGetSymbolAddress((void**)&Clo,  g_Clo);
    cudaGetSymbolAddress((void**)&Bbhi, g_Bbhi);
    cudaGetSymbolAddress((void**)&Bblo, g_Bblo);
    cudaGetSymbolAddress((void**)&Dshi, g_Dshi);
    cudaGetSymbolAddress((void**)&Dslo, g_Dslo);
    cudaGetSymbolAddress((void**)&Zh,   g_Zh);
    cudaGetSymbolAddress((void**)&Zl,   g_Zl);
    cudaGetSymbolAddress((void**)&Uh,   g_Uh);
    cudaGetSymbolAddress((void**)&Ul,   g_Ul);

    cudaFuncSetAttribute(scan_persist, cudaFuncAttributeMaxDynamicSharedMemorySize, SM_TOT);
    cudaFuncSetAttribute(gemm_tc, cudaFuncAttributeMaxDynamicSharedMemorySize, TC_TOT);

    const int n2 = DD*DD;
    const int g2 = (n2 + 255)/256;
    dim3 gg1(16, 8, 1), gg2(16, 8, 2);
    const float4 z4  = make_float4(0.f, 0.f, 0.f, 0.f);
    const float4 D2E = make_float4(2.4801587e-05f, 2.7557319e-06f, 2.7557319e-07f, 2.5052108e-08f);
    const float4 D1E = make_float4(4.1666667e-02f, 8.3333333e-03f, 1.3888889e-03f, 1.9841270e-04f);
    const float4 D0E = make_float4(1.f, 1.f, 0.5f, 1.6666667e-01f);
    const float4 D2P = make_float4(2.7557319e-06f, 2.7557319e-07f, 2.5052108e-08f, 2.0876757e-09f);
    const float4 D1P = make_float4(8.3333333e-03f, 1.3888889e-03f, 1.9841270e-04f, 2.4801587e-05f);
    const float4 D0P = make_float4(1.f, 0.5f, 1.6666667e-01f, 4.1666667e-02f);

    build_Y_kernel<<<g2, 256>>>(skew, gamma, dtp, Y_);
    split_T<<<g2, 256>>>(Y_, Yht, Ylt);

    gemm_tc<<<gg1, 256, TC_TOT>>>(Y_, Y_, Yht, Ylt, Yht, Ylt, Y2_, Y2_,
                                  Eht, Elt, Eht, Elt, 1, 0,
                                  Y_, Y2_, Y3_, z4, z4, 0);
    gemm_tc<<<gg2, 256, TC_TOT>>>(Y2_, Y2_, Yht, Ylt, Eht, Elt, Y3_, T_,
                                  Pht, Plt, Pht, Plt, 0, 1,
                                  Y_, Y2_, Y3_, z4, z4, 0);
    init_H<<<g2, 256>>>(Y_, Y2_, Y3_, E_, P_);
    gemm_tc<<<gg2, 256, TC_TOT>>>(E_, P_, Pht, Plt, Pht, Plt, T2_, T3_,
                                  Pht, Plt, Pht, Plt, 0, 0,
                                  Y_, Y2_, Y3_, D2E, D2P, 1);
    gemm_tc<<<gg2, 256, TC_TOT>>>(T2_, T3_, Pht, Plt, Pht, Plt, E_, P_,
                                  Pht, Plt, Pht, Plt, 0, 0,
                                  Y_, Y2_, Y3_, D1E, D1P, 1);
    gemm_tc<<<gg2, 256, TC_TOT>>>(E_, P_, Pht, Plt, Pht, Plt, T2_, T3_,
                                  Pht, Plt, Pht, Plt, 0, 0,
                                  Y_, Y2_, Y3_, D0E, D0P, 1);
    gemm_small<<<16, 256>>>(Bb_, T3_, B_ct);

    split_mat<<<g2, 256>>>(T2_, Ehi, Elo, DD, DD, DD, DD, dtp, 0);
    split_mat<<<(64*DD + 255)/256, 256>>>(Cm, Chi, Clo, NOBS, DD, 64, DD, dtp, 0);
    split_mat<<<(DD*64 + 255)/256, 256>>>(Bb_, Bbhi, Bblo, DD, UDIM, DD, 64, dtp, 1);
    split_mat<<<(64*64 + 255)/256, 256>>>(Dm, Dshi, Dslo, NOBS, UDIM, 64, 64, dtp, 1);
    split_mat<<<g2, 256>>>(z_dyn, Zh, Zl, BB, DD, BB, DD, dtp, 0);
    split_mat<<<(TT*BB*64 + 255)/256, 256>>>(U, Uh, Ul, TT*BB, UDIM, TT*BB, 64, dtp, 0);

    reset_barrier<<<1, 32>>>();

    float* Zo = (float*)d_out;
    float* Yo = (float*)d_out + (size_t)TT*BB*DD;
    scan_persist<<<NCTA, 256, SM_TOT>>>(Zo, Yo,
                                        Ehi, Elo, Bbhi, Bblo, Chi, Clo, Dshi, Dslo,
                                        Zh, Zl, Uh, Ul);
}